// round 6
// baseline (speedup 1.0000x reference)
#include <cuda_runtime.h>
#include <math.h>
#include <cstdint>

#define NN   16384
#define DD   16
#define FIN  512
#define FOUT 512
#define RR   8
#define HIDD 64
#define BN_EPS 1e-5f
#define RESIDUAL 0.12f

// ---------------- scratch (device globals: allocation-free) ----------------
__device__ float g_att  [(size_t)NN * RR * FIN];    // 268 MB (tf32-rounded)
__device__ float g_srcz [(size_t)NN * RR * FOUT];   // 268 MB
__device__ float g_hz   [(size_t)NN * FOUT];        // 33 MB
__device__ float g_msg  [2ull * NN * FOUT];         // 67 MB
__device__ float g_wt   [(size_t)FIN * FOUT];       // 1 MB (W^T, tf32-rounded)
__device__ float g_hconv[(size_t)NN * FIN];         // 33 MB (h, tf32-rounded)

__device__ __forceinline__ float lrelu(float x) { return x >= 0.0f ? x : 0.2f * x; }

__device__ __forceinline__ float to_tf32(float x) {
    float r;
    asm("cvt.rn.tf32.f32 %0, %1;" : "=f"(r) : "f"(x));
    return r;
}

__device__ __forceinline__ uint32_t smem_u32(const void* p) {
    uint32_t a;
    asm("{ .reg .u64 t; cvta.to.shared.u64 t, %1; cvt.u32.u64 %0, t; }" : "=r"(a) : "l"(p));
    return a;
}
__device__ __forceinline__ void cp_async16(uint32_t dst, const void* src) {
    asm volatile("cp.async.cg.shared.global [%0], [%1], 16;" :: "r"(dst), "l"(src));
}
#define CP_COMMIT() asm volatile("cp.async.commit_group;" ::: "memory")
#define CP_WAIT(n)  asm volatile("cp.async.wait_group %0;" :: "n"(n) : "memory")

__device__ __forceinline__ void ldsm_x4(uint32_t* r, uint32_t addr) {
    asm volatile("ldmatrix.sync.aligned.m8n8.x4.shared.b16 {%0,%1,%2,%3}, [%4];"
        : "=r"(r[0]), "=r"(r[1]), "=r"(r[2]), "=r"(r[3]) : "r"(addr));
}

__device__ __forceinline__ void mma_tf32(float& c0, float& c1, float& c2, float& c3,
                                         uint32_t a0, uint32_t a1, uint32_t a2, uint32_t a3,
                                         uint32_t b0, uint32_t b1) {
    asm volatile(
        "mma.sync.aligned.m16n8k8.row.col.f32.tf32.tf32.f32 "
        "{%0,%1,%2,%3}, {%4,%5,%6,%7}, {%8,%9}, {%0,%1,%2,%3};"
        : "+f"(c0), "+f"(c1), "+f"(c2), "+f"(c3)
        : "r"(a0), "r"(a1), "r"(a2), "r"(a3), "r"(b0), "r"(b1));
}

// ---------------- kernel 0a: transpose W [K,N] -> WT [N,K], tf32 round ----------------
__global__ void transposeW_kernel(const float* __restrict__ W, float* __restrict__ WT)
{
    __shared__ float t[32][33];
    int bx = blockIdx.x * 32, by = blockIdx.y * 32;
    t[threadIdx.y][threadIdx.x] = W[(by + threadIdx.y) * FOUT + bx + threadIdx.x];
    __syncthreads();
    WT[(bx + threadIdx.y) * FIN + by + threadIdx.x] = to_tf32(t[threadIdx.x][threadIdx.y]);
}

// ---------------- kernel 0b: round h to tf32 ----------------
__global__ void convert_kernel(const float* __restrict__ in, float* __restrict__ out, int n4)
{
    int i = blockIdx.x * blockDim.x + threadIdx.x;
    if (i < n4) {
        float4 v = reinterpret_cast<const float4*>(in)[i];
        v.x = to_tf32(v.x); v.y = to_tf32(v.y);
        v.z = to_tf32(v.z); v.w = to_tf32(v.w);
        reinterpret_cast<float4*>(out)[i] = v;
    }
}

// ---------------- kernel 1: relation maxpool (tf32-rounded output) ----------------
__global__ void maxpool_kernel(const float* __restrict__ src,
                               const int*   __restrict__ rel,
                               float*       __restrict__ att)
{
    int n   = blockIdx.x;
    int tid = threadIdx.x;  // 128

    __shared__ int rl[DD];
    __shared__ int cnt[RR];
    if (tid < RR) cnt[tid] = 0;
    __syncthreads();
    if (tid < DD) {
        int r = rel[n * DD + tid];
        rl[tid] = r;
        atomicAdd(&cnt[r], 1);
    }
    __syncthreads();

    const float4* sp = reinterpret_cast<const float4*>(src + (size_t)n * DD * FIN);
    const float NEG = -3.402823466e38f;

    float4 mx[RR];
#pragma unroll
    for (int r = 0; r < RR; r++) mx[r] = make_float4(NEG, NEG, NEG, NEG);

#pragma unroll
    for (int d = 0; d < DD; d++) {
        float4 v = sp[d * (FIN / 4) + tid];
        int rd = rl[d];
#pragma unroll
        for (int r = 0; r < RR; r++) {
            bool m = (rd == r);
            mx[r].x = m ? fmaxf(mx[r].x, v.x) : mx[r].x;
            mx[r].y = m ? fmaxf(mx[r].y, v.y) : mx[r].y;
            mx[r].z = m ? fmaxf(mx[r].z, v.z) : mx[r].z;
            mx[r].w = m ? fmaxf(mx[r].w, v.w) : mx[r].w;
        }
    }

    float4* ap = reinterpret_cast<float4*>(att + (size_t)n * RR * FIN);
#pragma unroll
    for (int r = 0; r < RR; r++) {
        float4 o = mx[r];
        if (cnt[r] != DD) {
            o.x = fmaxf(o.x, 0.0f);
            o.y = fmaxf(o.y, 0.0f);
            o.z = fmaxf(o.z, 0.0f);
            o.w = fmaxf(o.w, 0.0f);
        }
        o.x = to_tf32(o.x); o.y = to_tf32(o.y);
        o.z = to_tf32(o.z); o.w = to_tf32(o.w);
        ap[r * (FIN / 4) + tid] = o;
    }
}

// ---------------- kernel 2: mma.sync tf32 GEMM with ldmatrix fragments ----------------
// Fused: blocks y<512 compute srcz = lrelu(att @ WT^T); y>=512 compute hz from hconv.
// BM=256, BN=128, BK=16. 512 threads, 16 warps (4M x 4N), warp tile 64x32.
// 4-stage cp.async ring, one __syncthreads per stage.
#define TSTRIDE 20                               // smem row stride (floats)
#define STAGE_FLOATS ((256 + 128) * TSTRIDE)     // A tile + B tile per stage
#define GSTAGES 4
#define GEMM_SMEM (GSTAGES * STAGE_FLOATS * 4)   // 122880 bytes
#define MBBIG (NN * RR / 256)                    // 512 row-blocks for the big GEMM

__global__ void __launch_bounds__(512, 1)
gemm_tc_kernel(const float* __restrict__ Abig,
               const float* __restrict__ Asmall,
               const float* __restrict__ Bt,
               float*       __restrict__ Cbig,
               float*       __restrict__ Csmall)
{
    extern __shared__ float sm[];
    int tid  = threadIdx.x;
    int wid  = tid >> 5;
    int lane = tid & 31;
    int wm   = wid & 3;     // 4 row slabs of 64
    int wn   = wid >> 2;    // 4 col slabs of 32
    int g    = lane >> 2;
    int t    = lane & 3;
    int q    = lane >> 3;   // ldmatrix quadrant 0..3
    int lr   = lane & 7;

    int mb = blockIdx.y;
    const float* A;
    float* C;
    int bm;
    if (mb < MBBIG) { A = Abig;   C = Cbig;   bm = mb * 256; }
    else            { A = Asmall; C = Csmall; bm = (mb - MBBIG) * 256; }
    int bn = blockIdx.x * 128;

    int row0 = tid >> 2;              // 0..127
    int kc0  = (tid & 3) * 4;         // 0,4,8,12
    const float* Ag0 = A  + (size_t)(bm + row0)       * FIN + kc0;
    const float* Ag1 = A  + (size_t)(bm + row0 + 128) * FIN + kc0;
    const float* Bg0 = Bt + (size_t)(bn + row0)       * FIN + kc0;

    uint32_t sbase = smem_u32(sm);
    uint32_t dA0 = sbase + (uint32_t)(row0 * TSTRIDE + kc0) * 4;
    uint32_t dA1 = dA0 + (uint32_t)(128 * TSTRIDE) * 4;
    uint32_t dB0 = sbase + (uint32_t)((256 + row0) * TSTRIDE + kc0) * 4;
    const uint32_t stageB = STAGE_FLOATS * 4;

    // ldmatrix per-lane source offsets (bytes) within a stage
    uint32_t laneAoff = (uint32_t)((wm * 64 + (q & 1) * 8 + lr) * TSTRIDE + (q >> 1) * 4) * 4;
    uint32_t laneBoff = (uint32_t)((256 + wn * 32 + (q >> 1) * 8 + lr) * TSTRIDE + (q & 1) * 4) * 4;

    float acc[4][4][4];
#pragma unroll
    for (int i = 0; i < 4; i++)
#pragma unroll
        for (int j = 0; j < 4; j++)
#pragma unroll
            for (int x = 0; x < 4; x++) acc[i][j][x] = 0.0f;

    const int NK = FIN / 16;  // 32 stages

    // prologue: stages 0..2
#pragma unroll
    for (int s = 0; s < GSTAGES - 1; s++) {
        int k0 = s * 16;
        uint32_t so = s * stageB;
        cp_async16(dA0 + so, Ag0 + k0);
        cp_async16(dA1 + so, Ag1 + k0);
        cp_async16(dB0 + so, Bg0 + k0);
        CP_COMMIT();
    }
    CP_WAIT(GSTAGES - 2);  // stage 0 ready

    for (int i = 0; i < NK; i++) {
        __syncthreads();

        if (i + GSTAGES - 1 < NK) {
            int k0 = (i + GSTAGES - 1) * 16;
            uint32_t so = ((i + GSTAGES - 1) & (GSTAGES - 1)) * stageB;
            cp_async16(dA0 + so, Ag0 + k0);
            cp_async16(dA1 + so, Ag1 + k0);
            cp_async16(dB0 + so, Bg0 + k0);
        }
        CP_COMMIT();

        uint32_t sa = sbase + (i & (GSTAGES - 1)) * stageB;
        uint32_t aA = sa + laneAoff;
        uint32_t aB = sa + laneBoff;
#pragma unroll
        for (int kk = 0; kk < 2; kk++) {
            uint32_t a[4][4];
            uint32_t b[2][4];
#pragma unroll
            for (int mt = 0; mt < 4; mt++)
                ldsm_x4(a[mt], aA + (uint32_t)(mt * 16 * TSTRIDE + kk * 8) * 4);
#pragma unroll
            for (int n2 = 0; n2 < 2; n2++)
                ldsm_x4(b[n2], aB + (uint32_t)(n2 * 16 * TSTRIDE + kk * 8) * 4);
#pragma unroll
            for (int mt = 0; mt < 4; mt++)
#pragma unroll
                for (int nt = 0; nt < 4; nt++)
                    mma_tf32(acc[mt][nt][0], acc[mt][nt][1], acc[mt][nt][2], acc[mt][nt][3],
                             a[mt][0], a[mt][1], a[mt][2], a[mt][3],
                             b[nt >> 1][(nt & 1) * 2], b[nt >> 1][(nt & 1) * 2 + 1]);
        }

        CP_WAIT(GSTAGES - 2);
    }

    // ---- epilogue: lrelu + store ----
#pragma unroll
    for (int mt = 0; mt < 4; mt++) {
        int mrow = bm + wm * 64 + mt * 16 + g;
#pragma unroll
        for (int nt = 0; nt < 4; nt++) {
            int ncol = bn + wn * 32 + nt * 8 + t * 2;
            float2 lo, hi;
            lo.x = lrelu(acc[mt][nt][0]);
            lo.y = lrelu(acc[mt][nt][1]);
            hi.x = lrelu(acc[mt][nt][2]);
            hi.y = lrelu(acc[mt][nt][3]);
            *reinterpret_cast<float2*>(C + (size_t)mrow * FOUT + ncol)       = lo;
            *reinterpret_cast<float2*>(C + (size_t)(mrow + 8) * FOUT + ncol) = hi;
        }
    }
}

// ---------------- kernel 3: GAT softmax epilogue (9 warps, 1 dot per warp) ----------------
__global__ void gat_epilogue_kernel(const float* __restrict__ srcz,
                                    const float* __restrict__ hz,
                                    const float* __restrict__ a_attn,
                                    float*       __restrict__ msg)
{
    int n   = blockIdx.x;
    int tid = threadIdx.x;  // 288 = 9 warps
    int warp = tid >> 5, lane = tid & 31;

    __shared__ float zs[RR][FOUT];
    __shared__ float hzs[FOUT];
    __shared__ float scoresm[9];
    __shared__ float alpha[RR];

    const float4* zp4 = reinterpret_cast<const float4*>(srcz + (size_t)n * RR * FOUT);
    float4* zs4 = reinterpret_cast<float4*>(&zs[0][0]);
    for (int i = tid; i < RR * FOUT / 4; i += 288) zs4[i] = zp4[i];
    const float4* hp4 = reinterpret_cast<const float4*>(hz + (size_t)n * FOUT);
    float4* hzs4 = reinterpret_cast<float4*>(hzs);
    for (int i = tid; i < FOUT / 4; i += 288) hzs4[i] = hp4[i];
    __syncthreads();

    {
        const float4* src4 = (warp < 8) ? reinterpret_cast<const float4*>(&zs[warp][0])
                                        : reinterpret_cast<const float4*>(hzs);
        const float4* a4 = reinterpret_cast<const float4*>(a_attn + (warp < 8 ? 0 : FOUT));
        float s = 0.0f;
#pragma unroll
        for (int c = 0; c < 4; c++) {
            float4 z4 = src4[lane + c * 32];
            float4 av = a4[lane + c * 32];
            s += z4.x * av.x + z4.y * av.y + z4.z * av.z + z4.w * av.w;
        }
#pragma unroll
        for (int off = 16; off; off >>= 1)
            s += __shfl_down_sync(0xffffffffu, s, off);
        if (lane == 0) scoresm[warp] = s;
    }
    __syncthreads();

    if (tid == 0) {
        float sh = scoresm[8];
        float sc[RR], mx = -3.402823466e38f;
#pragma unroll
        for (int r = 0; r < RR; r++) {
            sc[r] = lrelu(scoresm[r] + sh);
            mx = fmaxf(mx, sc[r]);
        }
        float sum = 0.0f;
#pragma unroll
        for (int r = 0; r < RR; r++) {
            float e = expf(sc[r] - mx);
            alpha[r] = e;
            sum += e;
        }
        float inv = 1.0f / sum;
#pragma unroll
        for (int r = 0; r < RR; r++) alpha[r] *= inv;
    }
    __syncthreads();

    float al[RR];
#pragma unroll
    for (int r = 0; r < RR; r++) al[r] = alpha[r];

    for (int f = tid; f < FOUT; f += 288) {
        float acc = RESIDUAL * hzs[f];
#pragma unroll
        for (int r = 0; r < RR; r++) acc += al[r] * zs[r][f];
        msg[(size_t)n * FOUT + f] = acc;
    }
}

// ---------------- kernel 4: multi-attention + BatchNorm ----------------
__global__ void final_kernel(const float* __restrict__ Wp1,
                             const float* __restrict__ bp1,
                             const float* __restrict__ Wp2,
                             const float* __restrict__ bp2,
                             const float* __restrict__ gamma,
                             const float* __restrict__ betaBN,
                             const float* __restrict__ mean,
                             const float* __restrict__ var,
                             float*       __restrict__ out)
{
    int n   = blockIdx.x;
    int tid = threadIdx.x;  // 128

    __shared__ float z[2][FOUT];
    __shared__ float wred[4];
    __shared__ float betasm[2];

    for (int f = tid; f < FOUT; f += 128) {
        z[0][f] = g_msg[(size_t)n * FOUT + f];
        z[1][f] = g_msg[(size_t)NN * FOUT + (size_t)n * FOUT + f];
    }
    __syncthreads();

    int i  = tid >> 6;
    int hd = tid & 63;
    float acc = 0.0f;
#pragma unroll 8
    for (int k = 0; k < FOUT; k++) acc += z[i][k] * Wp1[k * HIDD + hd];
    float t  = tanhf(acc + bp1[hd]);
    float pw = t * Wp2[hd];

#pragma unroll
    for (int off = 16; off; off >>= 1)
        pw += __shfl_down_sync(0xffffffffu, pw, off);
    if ((tid & 31) == 0) wred[tid >> 5] = pw;
    __syncthreads();
    if (tid == 0) {
        float w0 = tanhf(wred[0] + wred[1] + bp2[0]);
        float w1 = tanhf(wred[2] + wred[3] + bp2[0]);
        float m  = fmaxf(w0, w1);
        float e0 = expf(w0 - m), e1 = expf(w1 - m);
        float inv = 1.0f / (e0 + e1);
        betasm[0] = e0 * inv;
        betasm[1] = e1 * inv;
    }
    __syncthreads();

    float b0 = betasm[0], b1 = betasm[1];
    for (int f = tid; f < FOUT; f += 128) {
        float v = b0 * z[0][f] + b1 * z[1][f];
        out[(size_t)n * FOUT + f] =
            (v - mean[f]) * rsqrtf(var[f] + BN_EPS) * gamma[f] + betaBN[f];
    }
}

// ---------------- launch ----------------
extern "C" void kernel_launch(void* const* d_in, const int* in_sizes, int n_in,
                              void* d_out, int out_size)
{
    const float* src_h     = (const float*)d_in[0];
    const float* src_h_img = (const float*)d_in[1];
    const int*   rel       = (const int*)  d_in[2];
    const float* h         = (const float*)d_in[3];
    const float* h_img     = (const float*)d_in[4];
    const float* W0        = (const float*)d_in[5];
    const float* a0        = (const float*)d_in[6];
    const float* W1        = (const float*)d_in[7];
    const float* a1        = (const float*)d_in[8];
    const float* Wp1       = (const float*)d_in[9];
    const float* bp1       = (const float*)d_in[10];
    const float* Wp2       = (const float*)d_in[11];
    const float* bp2       = (const float*)d_in[12];
    const float* gamma     = (const float*)d_in[13];
    const float* betaBN    = (const float*)d_in[14];
    const float* mean      = (const float*)d_in[15];
    const float* var       = (const float*)d_in[16];
    float* out = (float*)d_out;

    float *att, *srcz, *hz, *msg, *wt, *hconv;
    cudaGetSymbolAddress((void**)&att,   g_att);
    cudaGetSymbolAddress((void**)&srcz,  g_srcz);
    cudaGetSymbolAddress((void**)&hz,    g_hz);
    cudaGetSymbolAddress((void**)&msg,   g_msg);
    cudaGetSymbolAddress((void**)&wt,    g_wt);
    cudaGetSymbolAddress((void**)&hconv, g_hconv);

    static bool attr_set = false;
    if (!attr_set) {
        cudaFuncSetAttribute(gemm_tc_kernel,
                             cudaFuncAttributeMaxDynamicSharedMemorySize, GEMM_SMEM);
        attr_set = true;
    }

    const float* srcs[2] = {src_h, src_h_img};
    const float* hs[2]   = {h, h_img};
    const float* Ws[2]   = {W0, W1};
    const float* as[2]   = {a0, a1};

    for (int pass = 0; pass < 2; pass++) {
        transposeW_kernel<<<dim3(16, 16), dim3(32, 32)>>>(Ws[pass], wt);
        convert_kernel<<<(NN * FIN / 4 + 255) / 256, 256>>>(hs[pass], hconv, NN * FIN / 4);
        maxpool_kernel<<<NN, 128>>>(srcs[pass], rel, att);
        gemm_tc_kernel<<<dim3(FOUT / 128, MBBIG + NN / 256), 512, GEMM_SMEM>>>(
            att, hconv, wt, srcz, hz);
        gat_epilogue_kernel<<<NN, 288>>>(srcz, hz, as[pass],
                                         msg + (size_t)pass * NN * FOUT);
    }
    final_kernel<<<NN, 128>>>(Wp1, bp1, Wp2, bp2, gamma, betaBN, mean, var, out);
}

// round 7
// speedup vs baseline: 1.0836x; 1.0836x over previous
#include <cuda_runtime.h>
#include <math.h>
#include <cstdint>

#define NN   16384
#define DD   16
#define FIN  512
#define FOUT 512
#define RR   8
#define HIDD 64
#define BN_EPS 1e-5f
#define RESIDUAL 0.12f

// ---------------- scratch (device globals: allocation-free) ----------------
__device__ float g_att  [(size_t)NN * RR * FIN];    // 268 MB (tf32-rounded)
__device__ float g_srcz [(size_t)NN * RR * FOUT];   // 268 MB
__device__ float g_hz   [(size_t)NN * FOUT];        // 33 MB
__device__ float g_msg  [2ull * NN * FOUT];         // 67 MB
__device__ float g_wt   [(size_t)FIN * FOUT];       // 1 MB (W^T, tf32-rounded)
__device__ float g_hconv[(size_t)NN * FIN];         // 33 MB (h, tf32-rounded)

__device__ __forceinline__ float lrelu(float x) { return x >= 0.0f ? x : 0.2f * x; }

__device__ __forceinline__ float to_tf32(float x) {
    float r;
    asm("cvt.rn.tf32.f32 %0, %1;" : "=f"(r) : "f"(x));
    return r;
}

__device__ __forceinline__ uint32_t smem_u32(const void* p) {
    uint32_t a;
    asm("{ .reg .u64 t; cvta.to.shared.u64 t, %1; cvt.u32.u64 %0, t; }" : "=r"(a) : "l"(p));
    return a;
}
__device__ __forceinline__ void cp_async16(uint32_t dst, const void* src) {
    asm volatile("cp.async.cg.shared.global [%0], [%1], 16;" :: "r"(dst), "l"(src));
}
#define CP_COMMIT() asm volatile("cp.async.commit_group;" ::: "memory")
#define CP_WAIT(n)  asm volatile("cp.async.wait_group %0;" :: "n"(n) : "memory")

__device__ __forceinline__ void ldsm_x4(uint32_t* r, uint32_t addr) {
    asm volatile("ldmatrix.sync.aligned.m8n8.x4.shared.b16 {%0,%1,%2,%3}, [%4];"
        : "=r"(r[0]), "=r"(r[1]), "=r"(r[2]), "=r"(r[3]) : "r"(addr));
}

__device__ __forceinline__ void mma_tf32(float& c0, float& c1, float& c2, float& c3,
                                         uint32_t a0, uint32_t a1, uint32_t a2, uint32_t a3,
                                         uint32_t b0, uint32_t b1) {
    asm volatile(
        "mma.sync.aligned.m16n8k8.row.col.f32.tf32.tf32.f32 "
        "{%0,%1,%2,%3}, {%4,%5,%6,%7}, {%8,%9}, {%0,%1,%2,%3};"
        : "+f"(c0), "+f"(c1), "+f"(c2), "+f"(c3)
        : "r"(a0), "r"(a1), "r"(a2), "r"(a3), "r"(b0), "r"(b1));
}

// ---------------- kernel 0a: transpose W [K,N] -> WT [N,K], tf32 round ----------------
__global__ void transposeW_kernel(const float* __restrict__ W, float* __restrict__ WT)
{
    __shared__ float t[32][33];
    int bx = blockIdx.x * 32, by = blockIdx.y * 32;
    t[threadIdx.y][threadIdx.x] = W[(by + threadIdx.y) * FOUT + bx + threadIdx.x];
    __syncthreads();
    WT[(bx + threadIdx.y) * FIN + by + threadIdx.x] = to_tf32(t[threadIdx.x][threadIdx.y]);
}

// ---------------- kernel 0b: round h to tf32 ----------------
__global__ void convert_kernel(const float* __restrict__ in, float* __restrict__ out, int n4)
{
    int i = blockIdx.x * blockDim.x + threadIdx.x;
    if (i < n4) {
        float4 v = reinterpret_cast<const float4*>(in)[i];
        v.x = to_tf32(v.x); v.y = to_tf32(v.y);
        v.z = to_tf32(v.z); v.w = to_tf32(v.w);
        reinterpret_cast<float4*>(out)[i] = v;
    }
}

// ---------------- kernel 1: relation maxpool (tf32-rounded output) ----------------
__global__ void maxpool_kernel(const float* __restrict__ src,
                               const int*   __restrict__ rel,
                               float*       __restrict__ att)
{
    int n   = blockIdx.x;
    int tid = threadIdx.x;  // 128

    __shared__ int rl[DD];
    __shared__ int cnt[RR];
    if (tid < RR) cnt[tid] = 0;
    __syncthreads();
    if (tid < DD) {
        int r = rel[n * DD + tid];
        rl[tid] = r;
        atomicAdd(&cnt[r], 1);
    }
    __syncthreads();

    const float4* sp = reinterpret_cast<const float4*>(src + (size_t)n * DD * FIN);
    const float NEG = -3.402823466e38f;

    float4 mx[RR];
#pragma unroll
    for (int r = 0; r < RR; r++) mx[r] = make_float4(NEG, NEG, NEG, NEG);

#pragma unroll
    for (int d = 0; d < DD; d++) {
        float4 v = sp[d * (FIN / 4) + tid];
        int rd = rl[d];
#pragma unroll
        for (int r = 0; r < RR; r++) {
            bool m = (rd == r);
            mx[r].x = m ? fmaxf(mx[r].x, v.x) : mx[r].x;
            mx[r].y = m ? fmaxf(mx[r].y, v.y) : mx[r].y;
            mx[r].z = m ? fmaxf(mx[r].z, v.z) : mx[r].z;
            mx[r].w = m ? fmaxf(mx[r].w, v.w) : mx[r].w;
        }
    }

    float4* ap = reinterpret_cast<float4*>(att + (size_t)n * RR * FIN);
#pragma unroll
    for (int r = 0; r < RR; r++) {
        float4 o = mx[r];
        if (cnt[r] != DD) {
            o.x = fmaxf(o.x, 0.0f);
            o.y = fmaxf(o.y, 0.0f);
            o.z = fmaxf(o.z, 0.0f);
            o.w = fmaxf(o.w, 0.0f);
        }
        o.x = to_tf32(o.x); o.y = to_tf32(o.y);
        o.z = to_tf32(o.z); o.w = to_tf32(o.w);
        ap[r * (FIN / 4) + tid] = o;
    }
}

// ---------------- kernel 2: mma.sync tf32 GEMM with ldmatrix fragments ----------------
// Fused: blocks y<1024 compute srcz = lrelu(att @ WT^T); y>=1024 compute hz from hconv.
// BM=128, BN=128, BK=32. 256 threads, 8 warps (2M x 4N), warp tile 64x32.
// 3-stage cp.async ring, one __syncthreads per BK=32 stage (16 stages total).
#define TSTRIDE 36                               // smem row stride (floats), 32 data + 4 pad
#define STAGE_FLOATS ((128 + 128) * TSTRIDE)     // A tile + B tile per stage = 9216
#define GSTAGES 3
#define GEMM_SMEM (GSTAGES * STAGE_FLOATS * 4)   // 110592 bytes
#define MBBIG (NN * RR / 128)                    // 1024 row-blocks for the big GEMM

__global__ void __launch_bounds__(256, 2)
gemm_tc_kernel(const float* __restrict__ Abig,
               const float* __restrict__ Asmall,
               const float* __restrict__ Bt,
               float*       __restrict__ Cbig,
               float*       __restrict__ Csmall)
{
    extern __shared__ float sm[];
    int tid  = threadIdx.x;
    int wid  = tid >> 5;
    int lane = tid & 31;
    int wm   = wid & 1;     // 2 row slabs of 64
    int wn   = wid >> 1;    // 4 col slabs of 32
    int g    = lane >> 2;
    int t    = lane & 3;
    int q    = lane >> 3;   // ldmatrix quadrant 0..3
    int lr   = lane & 7;

    int mb = blockIdx.y;
    const float* A;
    float* C;
    int bm;
    if (mb < MBBIG) { A = Abig;   C = Cbig;   bm = mb * 128; }
    else            { A = Asmall; C = Csmall; bm = (mb - MBBIG) * 128; }
    int bn = blockIdx.x * 128;

    // stage copy: 128 rows x 32 floats = 1024 float4 per operand; 4 per thread each
    int row0 = tid >> 3;              // 0..31
    int kc0  = (tid & 7) * 4;         // 0..28
    const float* Ag = A  + (size_t)(bm + row0) * FIN + kc0;
    const float* Bg = Bt + (size_t)(bn + row0) * FIN + kc0;

    uint32_t sbase = smem_u32(sm);
    uint32_t dA = sbase + (uint32_t)(row0 * TSTRIDE + kc0) * 4;
    uint32_t dB = sbase + (uint32_t)((128 + row0) * TSTRIDE + kc0) * 4;
    const uint32_t stageB = STAGE_FLOATS * 4;
    const uint32_t rowblkB = (uint32_t)(32 * TSTRIDE) * 4;   // 32 rows of smem
    const size_t   rowblkG = (size_t)32 * FIN;               // 32 rows of gmem

    // ldmatrix per-lane source offsets (bytes) within a stage
    uint32_t laneAoff = (uint32_t)((wm * 64 + (q & 1) * 8 + lr) * TSTRIDE + (q >> 1) * 4) * 4;
    uint32_t laneBoff = (uint32_t)((128 + wn * 32 + (q >> 1) * 8 + lr) * TSTRIDE + (q & 1) * 4) * 4;

    float acc[4][4][4];
#pragma unroll
    for (int i = 0; i < 4; i++)
#pragma unroll
        for (int j = 0; j < 4; j++)
#pragma unroll
            for (int x = 0; x < 4; x++) acc[i][j][x] = 0.0f;

    const int NK = FIN / 32;  // 16 stages

    // prologue: stages 0..1
#pragma unroll
    for (int s = 0; s < GSTAGES - 1; s++) {
        int k0 = s * 32;
        uint32_t so = s * stageB;
#pragma unroll
        for (int j = 0; j < 4; j++) {
            cp_async16(dA + so + j * rowblkB, Ag + j * rowblkG + k0);
            cp_async16(dB + so + j * rowblkB, Bg + j * rowblkG + k0);
        }
        CP_COMMIT();
    }
    CP_WAIT(GSTAGES - 2);  // stage 0 ready

    int buf = 0, lbuf = GSTAGES - 1;
    for (int i = 0; i < NK; i++) {
        __syncthreads();

        if (i + GSTAGES - 1 < NK) {
            int k0 = (i + GSTAGES - 1) * 32;
            uint32_t so = lbuf * stageB;
#pragma unroll
            for (int j = 0; j < 4; j++) {
                cp_async16(dA + so + j * rowblkB, Ag + j * rowblkG + k0);
                cp_async16(dB + so + j * rowblkB, Bg + j * rowblkG + k0);
            }
        }
        CP_COMMIT();

        uint32_t sa = sbase + buf * stageB;
        uint32_t aA = sa + laneAoff;
        uint32_t aB = sa + laneBoff;
#pragma unroll
        for (int kk = 0; kk < 4; kk++) {
            uint32_t a[4][4];
            uint32_t b[2][4];
#pragma unroll
            for (int mt = 0; mt < 4; mt++)
                ldsm_x4(a[mt], aA + (uint32_t)(mt * 16 * TSTRIDE + kk * 8) * 4);
#pragma unroll
            for (int n2 = 0; n2 < 2; n2++)
                ldsm_x4(b[n2], aB + (uint32_t)(n2 * 16 * TSTRIDE + kk * 8) * 4);
#pragma unroll
            for (int mt = 0; mt < 4; mt++)
#pragma unroll
                for (int nt = 0; nt < 4; nt++)
                    mma_tf32(acc[mt][nt][0], acc[mt][nt][1], acc[mt][nt][2], acc[mt][nt][3],
                             a[mt][0], a[mt][1], a[mt][2], a[mt][3],
                             b[nt >> 1][(nt & 1) * 2], b[nt >> 1][(nt & 1) * 2 + 1]);
        }

        CP_WAIT(GSTAGES - 2);
        buf  = (buf  == GSTAGES - 1) ? 0 : buf + 1;
        lbuf = (lbuf == GSTAGES - 1) ? 0 : lbuf + 1;
    }

    // ---- epilogue: lrelu + store ----
#pragma unroll
    for (int mt = 0; mt < 4; mt++) {
        int mrow = bm + wm * 64 + mt * 16 + g;
#pragma unroll
        for (int nt = 0; nt < 4; nt++) {
            int ncol = bn + wn * 32 + nt * 8 + t * 2;
            float2 lo, hi;
            lo.x = lrelu(acc[mt][nt][0]);
            lo.y = lrelu(acc[mt][nt][1]);
            hi.x = lrelu(acc[mt][nt][2]);
            hi.y = lrelu(acc[mt][nt][3]);
            *reinterpret_cast<float2*>(C + (size_t)mrow * FOUT + ncol)       = lo;
            *reinterpret_cast<float2*>(C + (size_t)(mrow + 8) * FOUT + ncol) = hi;
        }
    }
}

// ---------------- kernel 3: GAT softmax epilogue (9 warps, 1 dot per warp) ----------------
__global__ void gat_epilogue_kernel(const float* __restrict__ srcz,
                                    const float* __restrict__ hz,
                                    const float* __restrict__ a_attn,
                                    float*       __restrict__ msg)
{
    int n   = blockIdx.x;
    int tid = threadIdx.x;  // 288 = 9 warps
    int warp = tid >> 5, lane = tid & 31;

    __shared__ float zs[RR][FOUT];
    __shared__ float hzs[FOUT];
    __shared__ float scoresm[9];
    __shared__ float alpha[RR];

    const float4* zp4 = reinterpret_cast<const float4*>(srcz + (size_t)n * RR * FOUT);
    float4* zs4 = reinterpret_cast<float4*>(&zs[0][0]);
    for (int i = tid; i < RR * FOUT / 4; i += 288) zs4[i] = zp4[i];
    const float4* hp4 = reinterpret_cast<const float4*>(hz + (size_t)n * FOUT);
    float4* hzs4 = reinterpret_cast<float4*>(hzs);
    for (int i = tid; i < FOUT / 4; i += 288) hzs4[i] = hp4[i];
    __syncthreads();

    {
        const float4* src4 = (warp < 8) ? reinterpret_cast<const float4*>(&zs[warp][0])
                                        : reinterpret_cast<const float4*>(hzs);
        const float4* a4 = reinterpret_cast<const float4*>(a_attn + (warp < 8 ? 0 : FOUT));
        float s = 0.0f;
#pragma unroll
        for (int c = 0; c < 4; c++) {
            float4 z4 = src4[lane + c * 32];
            float4 av = a4[lane + c * 32];
            s += z4.x * av.x + z4.y * av.y + z4.z * av.z + z4.w * av.w;
        }
#pragma unroll
        for (int off = 16; off; off >>= 1)
            s += __shfl_down_sync(0xffffffffu, s, off);
        if (lane == 0) scoresm[warp] = s;
    }
    __syncthreads();

    if (tid == 0) {
        float sh = scoresm[8];
        float sc[RR], mx = -3.402823466e38f;
#pragma unroll
        for (int r = 0; r < RR; r++) {
            sc[r] = lrelu(scoresm[r] + sh);
            mx = fmaxf(mx, sc[r]);
        }
        float sum = 0.0f;
#pragma unroll
        for (int r = 0; r < RR; r++) {
            float e = expf(sc[r] - mx);
            alpha[r] = e;
            sum += e;
        }
        float inv = 1.0f / sum;
#pragma unroll
        for (int r = 0; r < RR; r++) alpha[r] *= inv;
    }
    __syncthreads();

    float al[RR];
#pragma unroll
    for (int r = 0; r < RR; r++) al[r] = alpha[r];

    for (int f = tid; f < FOUT; f += 288) {
        float acc = RESIDUAL * hzs[f];
#pragma unroll
        for (int r = 0; r < RR; r++) acc += al[r] * zs[r][f];
        msg[(size_t)n * FOUT + f] = acc;
    }
}

// ---------------- kernel 4: multi-attention + BatchNorm ----------------
__global__ void final_kernel(const float* __restrict__ Wp1,
                             const float* __restrict__ bp1,
                             const float* __restrict__ Wp2,
                             const float* __restrict__ bp2,
                             const float* __restrict__ gamma,
                             const float* __restrict__ betaBN,
                             const float* __restrict__ mean,
                             const float* __restrict__ var,
                             float*       __restrict__ out)
{
    int n   = blockIdx.x;
    int tid = threadIdx.x;  // 128

    __shared__ float z[2][FOUT];
    __shared__ float wred[4];
    __shared__ float betasm[2];

    for (int f = tid; f < FOUT; f += 128) {
        z[0][f] = g_msg[(size_t)n * FOUT + f];
        z[1][f] = g_msg[(size_t)NN * FOUT + (size_t)n * FOUT + f];
    }
    __syncthreads();

    int i  = tid >> 6;
    int hd = tid & 63;
    float acc = 0.0f;
#pragma unroll 8
    for (int k = 0; k < FOUT; k++) acc += z[i][k] * Wp1[k * HIDD + hd];
    float t  = tanhf(acc + bp1[hd]);
    float pw = t * Wp2[hd];

#pragma unroll
    for (int off = 16; off; off >>= 1)
        pw += __shfl_down_sync(0xffffffffu, pw, off);
    if ((tid & 31) == 0) wred[tid >> 5] = pw;
    __syncthreads();
    if (tid == 0) {
        float w0 = tanhf(wred[0] + wred[1] + bp2[0]);
        float w1 = tanhf(wred[2] + wred[3] + bp2[0]);
        float m  = fmaxf(w0, w1);
        float e0 = expf(w0 - m), e1 = expf(w1 - m);
        float inv = 1.0f / (e0 + e1);
        betasm[0] = e0 * inv;
        betasm[1] = e1 * inv;
    }
    __syncthreads();

    float b0 = betasm[0], b1 = betasm[1];
    for (int f = tid; f < FOUT; f += 128) {
        float v = b0 * z[0][f] + b1 * z[1][f];
        out[(size_t)n * FOUT + f] =
            (v - mean[f]) * rsqrtf(var[f] + BN_EPS) * gamma[f] + betaBN[f];
    }
}

// ---------------- launch ----------------
extern "C" void kernel_launch(void* const* d_in, const int* in_sizes, int n_in,
                              void* d_out, int out_size)
{
    const float* src_h     = (const float*)d_in[0];
    const float* src_h_img = (const float*)d_in[1];
    const int*   rel       = (const int*)  d_in[2];
    const float* h         = (const float*)d_in[3];
    const float* h_img     = (const float*)d_in[4];
    const float* W0        = (const float*)d_in[5];
    const float* a0        = (const float*)d_in[6];
    const float* W1        = (const float*)d_in[7];
    const float* a1        = (const float*)d_in[8];
    const float* Wp1       = (const float*)d_in[9];
    const float* bp1       = (const float*)d_in[10];
    const float* Wp2       = (const float*)d_in[11];
    const float* bp2       = (const float*)d_in[12];
    const float* gamma     = (const float*)d_in[13];
    const float* betaBN    = (const float*)d_in[14];
    const float* mean      = (const float*)d_in[15];
    const float* var       = (const float*)d_in[16];
    float* out = (float*)d_out;

    float *att, *srcz, *hz, *msg, *wt, *hconv;
    cudaGetSymbolAddress((void**)&att,   g_att);
    cudaGetSymbolAddress((void**)&srcz,  g_srcz);
    cudaGetSymbolAddress((void**)&hz,    g_hz);
    cudaGetSymbolAddress((void**)&msg,   g_msg);
    cudaGetSymbolAddress((void**)&wt,    g_wt);
    cudaGetSymbolAddress((void**)&hconv, g_hconv);

    static bool attr_set = false;
    if (!attr_set) {
        cudaFuncSetAttribute(gemm_tc_kernel,
                             cudaFuncAttributeMaxDynamicSharedMemorySize, GEMM_SMEM);
        attr_set = true;
    }

    const float* srcs[2] = {src_h, src_h_img};
    const float* hs[2]   = {h, h_img};
    const float* Ws[2]   = {W0, W1};
    const float* as[2]   = {a0, a1};

    for (int pass = 0; pass < 2; pass++) {
        transposeW_kernel<<<dim3(16, 16), dim3(32, 32)>>>(Ws[pass], wt);
        convert_kernel<<<(NN * FIN / 4 + 255) / 256, 256>>>(hs[pass], hconv, NN * FIN / 4);
        maxpool_kernel<<<NN, 128>>>(srcs[pass], rel, att);
        gemm_tc_kernel<<<dim3(FOUT / 128, MBBIG + NN / 128), 256, GEMM_SMEM>>>(
            att, hconv, wt, srcz, hz);
        gat_epilogue_kernel<<<NN, 288>>>(srcz, hz, as[pass],
                                         msg + (size_t)pass * NN * FOUT);
    }
    final_kernel<<<NN, 128>>>(Wp1, bp1, Wp2, bp2, gamma, betaBN, mean, var, out);
}

// round 8
// speedup vs baseline: 1.4889x; 1.3740x over previous
#include <cuda_runtime.h>
#include <cuda_fp16.h>
#include <math.h>
#include <cstdint>

#define NN   16384
#define DD   16
#define FIN  512
#define FOUT 512
#define RR   8
#define HIDD 64
#define BN_EPS 1e-5f
#define RESIDUAL 0.12f

// ---------------- scratch (device globals: allocation-free) ----------------
__device__ __half g_att  [(size_t)NN * RR * FIN];   // 134 MB (fp16)
__device__ float  g_srcz [(size_t)NN * RR * FOUT];  // 268 MB
__device__ float  g_hz   [(size_t)NN * FOUT];       // 33 MB
__device__ float  g_msg  [2ull * NN * FOUT];        // 67 MB
__device__ __half g_wt   [(size_t)FIN * FOUT];      // 0.5 MB (W^T fp16)
__device__ __half g_hconv[(size_t)NN * FIN];        // 17 MB (h fp16)

__device__ __forceinline__ float lrelu(float x) { return x >= 0.0f ? x : 0.2f * x; }

__device__ __forceinline__ uint32_t smem_u32(const void* p) {
    uint32_t a;
    asm("{ .reg .u64 t; cvta.to.shared.u64 t, %1; cvt.u32.u64 %0, t; }" : "=r"(a) : "l"(p));
    return a;
}
__device__ __forceinline__ void cp_async16(uint32_t dst, const void* src) {
    asm volatile("cp.async.cg.shared.global [%0], [%1], 16;" :: "r"(dst), "l"(src));
}
#define CP_COMMIT() asm volatile("cp.async.commit_group;" ::: "memory")
#define CP_WAIT(n)  asm volatile("cp.async.wait_group %0;" :: "n"(n) : "memory")

__device__ __forceinline__ void ldsm_x4(uint32_t* r, uint32_t addr) {
    asm volatile("ldmatrix.sync.aligned.m8n8.x4.shared.b16 {%0,%1,%2,%3}, [%4];"
        : "=r"(r[0]), "=r"(r[1]), "=r"(r[2]), "=r"(r[3]) : "r"(addr));
}

__device__ __forceinline__ void mma_f16(float& c0, float& c1, float& c2, float& c3,
                                        uint32_t a0, uint32_t a1, uint32_t a2, uint32_t a3,
                                        uint32_t b0, uint32_t b1) {
    asm volatile(
        "mma.sync.aligned.m16n8k16.row.col.f32.f16.f16.f32 "
        "{%0,%1,%2,%3}, {%4,%5,%6,%7}, {%8,%9}, {%0,%1,%2,%3};"
        : "+f"(c0), "+f"(c1), "+f"(c2), "+f"(c3)
        : "r"(a0), "r"(a1), "r"(a2), "r"(a3), "r"(b0), "r"(b1));
}

// ---------------- kernel 0a: transpose W [K,N] -> WT [N,K], fp16 ----------------
__global__ void transposeW_kernel(const float* __restrict__ W, __half* __restrict__ WT)
{
    __shared__ float t[32][33];
    int bx = blockIdx.x * 32, by = blockIdx.y * 32;
    t[threadIdx.y][threadIdx.x] = W[(by + threadIdx.y) * FOUT + bx + threadIdx.x];
    __syncthreads();
    WT[(bx + threadIdx.y) * FIN + by + threadIdx.x] = __float2half_rn(t[threadIdx.x][threadIdx.y]);
}

// ---------------- kernel 0b: convert h to fp16 ----------------
__global__ void convert_kernel(const float* __restrict__ in, __half* __restrict__ out, int n4)
{
    int i = blockIdx.x * blockDim.x + threadIdx.x;
    if (i < n4) {
        float4 v = reinterpret_cast<const float4*>(in)[i];
        __half2 h0 = __floats2half2_rn(v.x, v.y);
        __half2 h1 = __floats2half2_rn(v.z, v.w);
        uint2 st;
        st.x = *reinterpret_cast<uint32_t*>(&h0);
        st.y = *reinterpret_cast<uint32_t*>(&h1);
        reinterpret_cast<uint2*>(out)[i] = st;
    }
}

// ---------------- kernel 1: relation maxpool (fp16 output) ----------------
__global__ void maxpool_kernel(const float* __restrict__ src,
                               const int*   __restrict__ rel,
                               __half*      __restrict__ att)
{
    int n   = blockIdx.x;
    int tid = threadIdx.x;  // 128

    __shared__ int rl[DD];
    __shared__ int cnt[RR];
    if (tid < RR) cnt[tid] = 0;
    __syncthreads();
    if (tid < DD) {
        int r = rel[n * DD + tid];
        rl[tid] = r;
        atomicAdd(&cnt[r], 1);
    }
    __syncthreads();

    const float4* sp = reinterpret_cast<const float4*>(src + (size_t)n * DD * FIN);
    const float NEG = -3.402823466e38f;

    float4 mx[RR];
#pragma unroll
    for (int r = 0; r < RR; r++) mx[r] = make_float4(NEG, NEG, NEG, NEG);

#pragma unroll
    for (int d = 0; d < DD; d++) {
        float4 v = sp[d * (FIN / 4) + tid];
        int rd = rl[d];
#pragma unroll
        for (int r = 0; r < RR; r++) {
            bool m = (rd == r);
            mx[r].x = m ? fmaxf(mx[r].x, v.x) : mx[r].x;
            mx[r].y = m ? fmaxf(mx[r].y, v.y) : mx[r].y;
            mx[r].z = m ? fmaxf(mx[r].z, v.z) : mx[r].z;
            mx[r].w = m ? fmaxf(mx[r].w, v.w) : mx[r].w;
        }
    }

    uint2* ap = reinterpret_cast<uint2*>(att + (size_t)n * RR * FIN);
#pragma unroll
    for (int r = 0; r < RR; r++) {
        float4 o = mx[r];
        if (cnt[r] != DD) {
            o.x = fmaxf(o.x, 0.0f);
            o.y = fmaxf(o.y, 0.0f);
            o.z = fmaxf(o.z, 0.0f);
            o.w = fmaxf(o.w, 0.0f);
        }
        __half2 h0 = __floats2half2_rn(o.x, o.y);
        __half2 h1 = __floats2half2_rn(o.z, o.w);
        uint2 st;
        st.x = *reinterpret_cast<uint32_t*>(&h0);
        st.y = *reinterpret_cast<uint32_t*>(&h1);
        ap[r * (FIN / 4) + tid] = st;
    }
}

// ---------------- kernel 2: mma.sync fp16 GEMM with ldmatrix fragments ----------------
// Fused: blocks y<1024 compute srcz = lrelu(att @ WT^T); y>=1024 compute hz from hconv.
// BM=128, BN=128, BK=64 (halfs). 256 threads, 8 warps (2M x 4N), warp tile 64x32.
// 3-stage cp.async ring, one __syncthreads per stage (8 stages total).
#define TSH 72                                   // smem row stride (halfs): 64 data + 8 pad
#define STAGE_HALFS ((128 + 128) * TSH)          // 18432 halfs = 36864 B
#define GSTAGES 3
#define GEMM_SMEM (GSTAGES * STAGE_HALFS * 2)    // 110592 bytes
#define MBBIG (NN * RR / 128)                    // 1024 row-blocks for the big GEMM

__global__ void __launch_bounds__(256, 2)
gemm_tc_kernel(const __half* __restrict__ Abig,
               const __half* __restrict__ Asmall,
               const __half* __restrict__ Bt,
               float*        __restrict__ Cbig,
               float*        __restrict__ Csmall)
{
    extern __shared__ __half smh[];
    int tid  = threadIdx.x;
    int wid  = tid >> 5;
    int lane = tid & 31;
    int wm   = wid & 1;     // 2 row slabs of 64
    int wn   = wid >> 1;    // 4 col slabs of 32
    int g    = lane >> 2;
    int t    = lane & 3;
    int q    = lane >> 3;   // ldmatrix quadrant 0..3
    int lr   = lane & 7;

    int mb = blockIdx.y;
    const __half* A;
    float* C;
    int bm;
    if (mb < MBBIG) { A = Abig;   C = Cbig;   bm = mb * 128; }
    else            { A = Asmall; C = Csmall; bm = (mb - MBBIG) * 128; }
    int bn = blockIdx.x * 128;

    // stage copy: 128 rows x 64 halfs (128B) per operand = 8 chunks of 16B per row
    int row0 = tid >> 3;              // 0..31
    int kc0  = (tid & 7) * 8;         // halfs: 0..56
    const __half* Ag = A  + (size_t)(bm + row0) * FIN + kc0;
    const __half* Bg = Bt + (size_t)(bn + row0) * FIN + kc0;

    uint32_t sbase = smem_u32(smh);
    uint32_t dA = sbase + (uint32_t)(row0 * TSH + kc0) * 2;
    uint32_t dB = sbase + (uint32_t)((128 + row0) * TSH + kc0) * 2;
    const uint32_t stageB  = STAGE_HALFS * 2;
    const uint32_t rowblkB = (uint32_t)(32 * TSH) * 2;   // 32 smem rows
    const size_t   rowblkG = (size_t)32 * FIN;           // 32 gmem rows (halfs)

    // ldmatrix per-lane source offsets (bytes) within a stage
    // A x4 quadrants: (q&1)->+8 rows, (q>>1)->+8 k-halfs (16B)
    uint32_t laneAoff = (uint32_t)((wm * 64 + (q & 1) * 8 + lr) * TSH + (q >> 1) * 8) * 2;
    // B x4: (q>>1)->+8 n rows, (q&1)->+8 k-halfs
    uint32_t laneBoff = (uint32_t)((128 + wn * 32 + (q >> 1) * 8 + lr) * TSH + (q & 1) * 8) * 2;

    float acc[4][4][4];
#pragma unroll
    for (int i = 0; i < 4; i++)
#pragma unroll
        for (int j = 0; j < 4; j++)
#pragma unroll
            for (int x = 0; x < 4; x++) acc[i][j][x] = 0.0f;

    const int NK = FIN / 64;  // 8 stages

    // prologue: stages 0..1
#pragma unroll
    for (int s = 0; s < GSTAGES - 1; s++) {
        int k0 = s * 64;
        uint32_t so = s * stageB;
#pragma unroll
        for (int j = 0; j < 4; j++) {
            cp_async16(dA + so + j * rowblkB, Ag + j * rowblkG + k0);
            cp_async16(dB + so + j * rowblkB, Bg + j * rowblkG + k0);
        }
        CP_COMMIT();
    }
    CP_WAIT(GSTAGES - 2);  // stage 0 ready

    int buf = 0, lbuf = GSTAGES - 1;
    for (int i = 0; i < NK; i++) {
        __syncthreads();

        if (i + GSTAGES - 1 < NK) {
            int k0 = (i + GSTAGES - 1) * 64;
            uint32_t so = lbuf * stageB;
#pragma unroll
            for (int j = 0; j < 4; j++) {
                cp_async16(dA + so + j * rowblkB, Ag + j * rowblkG + k0);
                cp_async16(dB + so + j * rowblkB, Bg + j * rowblkG + k0);
            }
        }
        CP_COMMIT();

        uint32_t sa = sbase + buf * stageB;
        uint32_t aA = sa + laneAoff;
        uint32_t aB = sa + laneBoff;
#pragma unroll
        for (int kk = 0; kk < 4; kk++) {   // 4 k16-steps per BK=64 stage
            uint32_t a[4][4];
            uint32_t b[2][4];
#pragma unroll
            for (int mt = 0; mt < 4; mt++)
                ldsm_x4(a[mt], aA + (uint32_t)(mt * 16 * TSH + kk * 16) * 2);
#pragma unroll
            for (int n2 = 0; n2 < 2; n2++)
                ldsm_x4(b[n2], aB + (uint32_t)(n2 * 16 * TSH + kk * 16) * 2);
#pragma unroll
            for (int mt = 0; mt < 4; mt++)
#pragma unroll
                for (int nt = 0; nt < 4; nt++)
                    mma_f16(acc[mt][nt][0], acc[mt][nt][1], acc[mt][nt][2], acc[mt][nt][3],
                            a[mt][0], a[mt][1], a[mt][2], a[mt][3],
                            b[nt >> 1][(nt & 1) * 2], b[nt >> 1][(nt & 1) * 2 + 1]);
        }

        CP_WAIT(GSTAGES - 2);
        buf  = (buf  == GSTAGES - 1) ? 0 : buf + 1;
        lbuf = (lbuf == GSTAGES - 1) ? 0 : lbuf + 1;
    }

    // ---- epilogue: lrelu + store (fp32) ----
#pragma unroll
    for (int mt = 0; mt < 4; mt++) {
        int mrow = bm + wm * 64 + mt * 16 + g;
#pragma unroll
        for (int nt = 0; nt < 4; nt++) {
            int ncol = bn + wn * 32 + nt * 8 + t * 2;
            float2 lo, hi;
            lo.x = lrelu(acc[mt][nt][0]);
            lo.y = lrelu(acc[mt][nt][1]);
            hi.x = lrelu(acc[mt][nt][2]);
            hi.y = lrelu(acc[mt][nt][3]);
            *reinterpret_cast<float2*>(C + (size_t)mrow * FOUT + ncol)       = lo;
            *reinterpret_cast<float2*>(C + (size_t)(mrow + 8) * FOUT + ncol) = hi;
        }
    }
}

// ---------------- kernel 3: GAT softmax epilogue (9 warps, 1 dot per warp) ----------------
__global__ void gat_epilogue_kernel(const float* __restrict__ srcz,
                                    const float* __restrict__ hz,
                                    const float* __restrict__ a_attn,
                                    float*       __restrict__ msg)
{
    int n   = blockIdx.x;
    int tid = threadIdx.x;  // 288 = 9 warps
    int warp = tid >> 5, lane = tid & 31;

    __shared__ float zs[RR][FOUT];
    __shared__ float hzs[FOUT];
    __shared__ float scoresm[9];
    __shared__ float alpha[RR];

    const float4* zp4 = reinterpret_cast<const float4*>(srcz + (size_t)n * RR * FOUT);
    float4* zs4 = reinterpret_cast<float4*>(&zs[0][0]);
    for (int i = tid; i < RR * FOUT / 4; i += 288) zs4[i] = zp4[i];
    const float4* hp4 = reinterpret_cast<const float4*>(hz + (size_t)n * FOUT);
    float4* hzs4 = reinterpret_cast<float4*>(hzs);
    for (int i = tid; i < FOUT / 4; i += 288) hzs4[i] = hp4[i];
    __syncthreads();

    {
        const float4* src4 = (warp < 8) ? reinterpret_cast<const float4*>(&zs[warp][0])
                                        : reinterpret_cast<const float4*>(hzs);
        const float4* a4 = reinterpret_cast<const float4*>(a_attn + (warp < 8 ? 0 : FOUT));
        float s = 0.0f;
#pragma unroll
        for (int c = 0; c < 4; c++) {
            float4 z4 = src4[lane + c * 32];
            float4 av = a4[lane + c * 32];
            s += z4.x * av.x + z4.y * av.y + z4.z * av.z + z4.w * av.w;
        }
#pragma unroll
        for (int off = 16; off; off >>= 1)
            s += __shfl_down_sync(0xffffffffu, s, off);
        if (lane == 0) scoresm[warp] = s;
    }
    __syncthreads();

    if (tid == 0) {
        float sh = scoresm[8];
        float sc[RR], mx = -3.402823466e38f;
#pragma unroll
        for (int r = 0; r < RR; r++) {
            sc[r] = lrelu(scoresm[r] + sh);
            mx = fmaxf(mx, sc[r]);
        }
        float sum = 0.0f;
#pragma unroll
        for (int r = 0; r < RR; r++) {
            float e = expf(sc[r] - mx);
            alpha[r] = e;
            sum += e;
        }
        float inv = 1.0f / sum;
#pragma unroll
        for (int r = 0; r < RR; r++) alpha[r] *= inv;
    }
    __syncthreads();

    float al[RR];
#pragma unroll
    for (int r = 0; r < RR; r++) al[r] = alpha[r];

    for (int f = tid; f < FOUT; f += 288) {
        float acc = RESIDUAL * hzs[f];
#pragma unroll
        for (int r = 0; r < RR; r++) acc += al[r] * zs[r][f];
        msg[(size_t)n * FOUT + f] = acc;
    }
}

// ---------------- kernel 4: multi-attention + BatchNorm ----------------
__global__ void final_kernel(const float* __restrict__ Wp1,
                             const float* __restrict__ bp1,
                             const float* __restrict__ Wp2,
                             const float* __restrict__ bp2,
                             const float* __restrict__ gamma,
                             const float* __restrict__ betaBN,
                             const float* __restrict__ mean,
                             const float* __restrict__ var,
                             float*       __restrict__ out)
{
    int n   = blockIdx.x;
    int tid = threadIdx.x;  // 128

    __shared__ float z[2][FOUT];
    __shared__ float wred[4];
    __shared__ float betasm[2];

    for (int f = tid; f < FOUT; f += 128) {
        z[0][f] = g_msg[(size_t)n * FOUT + f];
        z[1][f] = g_msg[(size_t)NN * FOUT + (size_t)n * FOUT + f];
    }
    __syncthreads();

    int i  = tid >> 6;
    int hd = tid & 63;
    float acc = 0.0f;
#pragma unroll 8
    for (int k = 0; k < FOUT; k++) acc += z[i][k] * Wp1[k * HIDD + hd];
    float t  = tanhf(acc + bp1[hd]);
    float pw = t * Wp2[hd];

#pragma unroll
    for (int off = 16; off; off >>= 1)
        pw += __shfl_down_sync(0xffffffffu, pw, off);
    if ((tid & 31) == 0) wred[tid >> 5] = pw;
    __syncthreads();
    if (tid == 0) {
        float w0 = tanhf(wred[0] + wred[1] + bp2[0]);
        float w1 = tanhf(wred[2] + wred[3] + bp2[0]);
        float m  = fmaxf(w0, w1);
        float e0 = expf(w0 - m), e1 = expf(w1 - m);
        float inv = 1.0f / (e0 + e1);
        betasm[0] = e0 * inv;
        betasm[1] = e1 * inv;
    }
    __syncthreads();

    float b0 = betasm[0], b1 = betasm[1];
    for (int f = tid; f < FOUT; f += 128) {
        float v = b0 * z[0][f] + b1 * z[1][f];
        out[(size_t)n * FOUT + f] =
            (v - mean[f]) * rsqrtf(var[f] + BN_EPS) * gamma[f] + betaBN[f];
    }
}

// ---------------- launch ----------------
extern "C" void kernel_launch(void* const* d_in, const int* in_sizes, int n_in,
                              void* d_out, int out_size)
{
    const float* src_h     = (const float*)d_in[0];
    const float* src_h_img = (const float*)d_in[1];
    const int*   rel       = (const int*)  d_in[2];
    const float* h         = (const float*)d_in[3];
    const float* h_img     = (const float*)d_in[4];
    const float* W0        = (const float*)d_in[5];
    const float* a0        = (const float*)d_in[6];
    const float* W1        = (const float*)d_in[7];
    const float* a1        = (const float*)d_in[8];
    const float* Wp1       = (const float*)d_in[9];
    const float* bp1       = (const float*)d_in[10];
    const float* Wp2       = (const float*)d_in[11];
    const float* bp2       = (const float*)d_in[12];
    const float* gamma     = (const float*)d_in[13];
    const float* betaBN    = (const float*)d_in[14];
    const float* mean      = (const float*)d_in[15];
    const float* var       = (const float*)d_in[16];
    float* out = (float*)d_out;

    __half *att, *wt, *hconv;
    float *srcz, *hz, *msg;
    cudaGetSymbolAddress((void**)&att,   g_att);
    cudaGetSymbolAddress((void**)&srcz,  g_srcz);
    cudaGetSymbolAddress((void**)&hz,    g_hz);
    cudaGetSymbolAddress((void**)&msg,   g_msg);
    cudaGetSymbolAddress((void**)&wt,    g_wt);
    cudaGetSymbolAddress((void**)&hconv, g_hconv);

    static bool attr_set = false;
    if (!attr_set) {
        cudaFuncSetAttribute(gemm_tc_kernel,
                             cudaFuncAttributeMaxDynamicSharedMemorySize, GEMM_SMEM);
        attr_set = true;
    }

    const float* srcs[2] = {src_h, src_h_img};
    const float* hs[2]   = {h, h_img};
    const float* Ws[2]   = {W0, W1};
    const float* as[2]   = {a0, a1};

    for (int pass = 0; pass < 2; pass++) {
        transposeW_kernel<<<dim3(16, 16), dim3(32, 32)>>>(Ws[pass], wt);
        convert_kernel<<<(NN * FIN / 4 + 255) / 256, 256>>>(hs[pass], hconv, NN * FIN / 4);
        maxpool_kernel<<<NN, 128>>>(srcs[pass], rel, att);
        gemm_tc_kernel<<<dim3(FOUT / 128, MBBIG + NN / 128), 256, GEMM_SMEM>>>(
            att, hconv, wt, srcz, hz);
        gat_epilogue_kernel<<<NN, 288>>>(srcz, hz, as[pass],
                                         msg + (size_t)pass * NN * FOUT);
    }
    final_kernel<<<NN, 128>>>(Wp1, bp1, Wp2, bp2, gamma, betaBN, mean, var, out);
}

// round 9
// speedup vs baseline: 1.4953x; 1.0043x over previous
#include <cuda_runtime.h>
#include <cuda_fp16.h>
#include <math.h>
#include <cstdint>

#define NN   16384
#define DD   16
#define FIN  512
#define FOUT 512
#define RR   8
#define HIDD 64
#define BN_EPS 1e-5f
#define RESIDUAL 0.12f

// ---------------- scratch (device globals: allocation-free), per-pass ----------------
__device__ __half g_att  [2ull * NN * RR * FIN];    // 268 MB (fp16)
__device__ float  g_srcz [2ull * NN * RR * FOUT];   // 536 MB
__device__ float  g_hz   [2ull * NN * FOUT];        // 66 MB
__device__ float  g_msg  [2ull * NN * FOUT];        // 67 MB
__device__ __half g_wt   [2ull * FIN * FOUT];       // 1 MB
__device__ __half g_hconv[2ull * NN * FIN];         // 34 MB

__device__ __forceinline__ float lrelu(float x) { return x >= 0.0f ? x : 0.2f * x; }

__device__ __forceinline__ uint32_t smem_u32(const void* p) {
    uint32_t a;
    asm("{ .reg .u64 t; cvta.to.shared.u64 t, %1; cvt.u32.u64 %0, t; }" : "=r"(a) : "l"(p));
    return a;
}
__device__ __forceinline__ void cp_async16(uint32_t dst, const void* src) {
    asm volatile("cp.async.cg.shared.global [%0], [%1], 16;" :: "r"(dst), "l"(src));
}
#define CP_COMMIT() asm volatile("cp.async.commit_group;" ::: "memory")
#define CP_WAIT(n)  asm volatile("cp.async.wait_group %0;" :: "n"(n) : "memory")

__device__ __forceinline__ void ldsm_x4(uint32_t* r, uint32_t addr) {
    asm volatile("ldmatrix.sync.aligned.m8n8.x4.shared.b16 {%0,%1,%2,%3}, [%4];"
        : "=r"(r[0]), "=r"(r[1]), "=r"(r[2]), "=r"(r[3]) : "r"(addr));
}

__device__ __forceinline__ void mma_f16(float& c0, float& c1, float& c2, float& c3,
                                        uint32_t a0, uint32_t a1, uint32_t a2, uint32_t a3,
                                        uint32_t b0, uint32_t b1) {
    asm volatile(
        "mma.sync.aligned.m16n8k16.row.col.f32.f16.f16.f32 "
        "{%0,%1,%2,%3}, {%4,%5,%6,%7}, {%8,%9}, {%0,%1,%2,%3};"
        : "+f"(c0), "+f"(c1), "+f"(c2), "+f"(c3)
        : "r"(a0), "r"(a1), "r"(a2), "r"(a3), "r"(b0), "r"(b1));
}

// ---------------- kernel 0a: transpose W [K,N] -> WT [N,K], fp16 ----------------
__global__ void transposeW_kernel(const float* __restrict__ W, __half* __restrict__ WT)
{
    __shared__ float t[32][33];
    int bx = blockIdx.x * 32, by = blockIdx.y * 32;
    t[threadIdx.y][threadIdx.x] = W[(by + threadIdx.y) * FOUT + bx + threadIdx.x];
    __syncthreads();
    WT[(bx + threadIdx.y) * FIN + by + threadIdx.x] = __float2half_rn(t[threadIdx.x][threadIdx.y]);
}

// ---------------- kernel 0b: convert h to fp16 ----------------
__global__ void convert_kernel(const float* __restrict__ in, __half* __restrict__ out, int n4)
{
    int i = blockIdx.x * blockDim.x + threadIdx.x;
    if (i < n4) {
        float4 v = reinterpret_cast<const float4*>(in)[i];
        __half2 h0 = __floats2half2_rn(v.x, v.y);
        __half2 h1 = __floats2half2_rn(v.z, v.w);
        uint2 st;
        st.x = *reinterpret_cast<uint32_t*>(&h0);
        st.y = *reinterpret_cast<uint32_t*>(&h1);
        reinterpret_cast<uint2*>(out)[i] = st;
    }
}

// ---------------- kernel 1: relation maxpool (fp16 output) ----------------
__global__ void maxpool_kernel(const float* __restrict__ src,
                               const int*   __restrict__ rel,
                               __half*      __restrict__ att)
{
    int n   = blockIdx.x;
    int tid = threadIdx.x;  // 128

    __shared__ int rl[DD];
    __shared__ int cnt[RR];
    if (tid < RR) cnt[tid] = 0;
    __syncthreads();
    if (tid < DD) {
        int r = rel[n * DD + tid];
        rl[tid] = r;
        atomicAdd(&cnt[r], 1);
    }
    __syncthreads();

    const float4* sp = reinterpret_cast<const float4*>(src + (size_t)n * DD * FIN);
    const float NEG = -3.402823466e38f;

    float4 mx[RR];
#pragma unroll
    for (int r = 0; r < RR; r++) mx[r] = make_float4(NEG, NEG, NEG, NEG);

#pragma unroll
    for (int d = 0; d < DD; d++) {
        float4 v = sp[d * (FIN / 4) + tid];
        int rd = rl[d];
#pragma unroll
        for (int r = 0; r < RR; r++) {
            bool m = (rd == r);
            mx[r].x = m ? fmaxf(mx[r].x, v.x) : mx[r].x;
            mx[r].y = m ? fmaxf(mx[r].y, v.y) : mx[r].y;
            mx[r].z = m ? fmaxf(mx[r].z, v.z) : mx[r].z;
            mx[r].w = m ? fmaxf(mx[r].w, v.w) : mx[r].w;
        }
    }

    uint2* ap = reinterpret_cast<uint2*>(att + (size_t)n * RR * FIN);
#pragma unroll
    for (int r = 0; r < RR; r++) {
        float4 o = mx[r];
        if (cnt[r] != DD) {
            o.x = fmaxf(o.x, 0.0f);
            o.y = fmaxf(o.y, 0.0f);
            o.z = fmaxf(o.z, 0.0f);
            o.w = fmaxf(o.w, 0.0f);
        }
        __half2 h0 = __floats2half2_rn(o.x, o.y);
        __half2 h1 = __floats2half2_rn(o.z, o.w);
        uint2 st;
        st.x = *reinterpret_cast<uint32_t*>(&h0);
        st.y = *reinterpret_cast<uint32_t*>(&h1);
        ap[r * (FIN / 4) + tid] = st;
    }
}

// ---------------- kernel 2: mma.sync fp16 GEMM with ldmatrix fragments ----------------
// Fused: blocks y<1024 compute srcz = lrelu(att @ WT^T); y>=1024 compute hz from hconv.
// BM=128, BN=128, BK=64 (halfs). 256 threads, 8 warps (2M x 4N), warp tile 64x32.
// 3-stage cp.async ring, one __syncthreads per stage (8 stages total).
#define TSH 72                                   // smem row stride (halfs): 64 data + 8 pad
#define STAGE_HALFS ((128 + 128) * TSH)          // 18432 halfs = 36864 B
#define GSTAGES 3
#define GEMM_SMEM (GSTAGES * STAGE_HALFS * 2)    // 110592 bytes
#define MBBIG (NN * RR / 128)                    // 1024 row-blocks for the big GEMM

__global__ void __launch_bounds__(256, 2)
gemm_tc_kernel(const __half* __restrict__ Abig,
               const __half* __restrict__ Asmall,
               const __half* __restrict__ Bt,
               float*        __restrict__ Cbig,
               float*        __restrict__ Csmall)
{
    extern __shared__ __half smh[];
    int tid  = threadIdx.x;
    int wid  = tid >> 5;
    int lane = tid & 31;
    int wm   = wid & 1;     // 2 row slabs of 64
    int wn   = wid >> 1;    // 4 col slabs of 32
    int g    = lane >> 2;
    int t    = lane & 3;
    int q    = lane >> 3;   // ldmatrix quadrant 0..3
    int lr   = lane & 7;

    int mb = blockIdx.y;
    const __half* A;
    float* C;
    int bm;
    if (mb < MBBIG) { A = Abig;   C = Cbig;   bm = mb * 128; }
    else            { A = Asmall; C = Csmall; bm = (mb - MBBIG) * 128; }
    int bn = blockIdx.x * 128;

    // stage copy: 128 rows x 64 halfs (128B) per operand = 8 chunks of 16B per row
    int row0 = tid >> 3;              // 0..31
    int kc0  = (tid & 7) * 8;         // halfs: 0..56
    const __half* Ag = A  + (size_t)(bm + row0) * FIN + kc0;
    const __half* Bg = Bt + (size_t)(bn + row0) * FIN + kc0;

    uint32_t sbase = smem_u32(smh);
    uint32_t dA = sbase + (uint32_t)(row0 * TSH + kc0) * 2;
    uint32_t dB = sbase + (uint32_t)((128 + row0) * TSH + kc0) * 2;
    const uint32_t stageB  = STAGE_HALFS * 2;
    const uint32_t rowblkB = (uint32_t)(32 * TSH) * 2;   // 32 smem rows
    const size_t   rowblkG = (size_t)32 * FIN;           // 32 gmem rows (halfs)

    // ldmatrix per-lane source offsets (bytes) within a stage
    uint32_t laneAoff = (uint32_t)((wm * 64 + (q & 1) * 8 + lr) * TSH + (q >> 1) * 8) * 2;
    uint32_t laneBoff = (uint32_t)((128 + wn * 32 + (q >> 1) * 8 + lr) * TSH + (q & 1) * 8) * 2;

    float acc[4][4][4];
#pragma unroll
    for (int i = 0; i < 4; i++)
#pragma unroll
        for (int j = 0; j < 4; j++)
#pragma unroll
            for (int x = 0; x < 4; x++) acc[i][j][x] = 0.0f;

    const int NK = FIN / 64;  // 8 stages

    // prologue: stages 0..1
#pragma unroll
    for (int s = 0; s < GSTAGES - 1; s++) {
        int k0 = s * 64;
        uint32_t so = s * stageB;
#pragma unroll
        for (int j = 0; j < 4; j++) {
            cp_async16(dA + so + j * rowblkB, Ag + j * rowblkG + k0);
            cp_async16(dB + so + j * rowblkB, Bg + j * rowblkG + k0);
        }
        CP_COMMIT();
    }
    CP_WAIT(GSTAGES - 2);  // stage 0 ready

    int buf = 0, lbuf = GSTAGES - 1;
    for (int i = 0; i < NK; i++) {
        __syncthreads();

        if (i + GSTAGES - 1 < NK) {
            int k0 = (i + GSTAGES - 1) * 64;
            uint32_t so = lbuf * stageB;
#pragma unroll
            for (int j = 0; j < 4; j++) {
                cp_async16(dA + so + j * rowblkB, Ag + j * rowblkG + k0);
                cp_async16(dB + so + j * rowblkB, Bg + j * rowblkG + k0);
            }
        }
        CP_COMMIT();

        uint32_t sa = sbase + buf * stageB;
        uint32_t aA = sa + laneAoff;
        uint32_t aB = sa + laneBoff;
#pragma unroll
        for (int kk = 0; kk < 4; kk++) {   // 4 k16-steps per BK=64 stage
            uint32_t a[4][4];
            uint32_t b[2][4];
#pragma unroll
            for (int mt = 0; mt < 4; mt++)
                ldsm_x4(a[mt], aA + (uint32_t)(mt * 16 * TSH + kk * 16) * 2);
#pragma unroll
            for (int n2 = 0; n2 < 2; n2++)
                ldsm_x4(b[n2], aB + (uint32_t)(n2 * 16 * TSH + kk * 16) * 2);
#pragma unroll
            for (int mt = 0; mt < 4; mt++)
#pragma unroll
                for (int nt = 0; nt < 4; nt++)
                    mma_f16(acc[mt][nt][0], acc[mt][nt][1], acc[mt][nt][2], acc[mt][nt][3],
                            a[mt][0], a[mt][1], a[mt][2], a[mt][3],
                            b[nt >> 1][(nt & 1) * 2], b[nt >> 1][(nt & 1) * 2 + 1]);
        }

        CP_WAIT(GSTAGES - 2);
        buf  = (buf  == GSTAGES - 1) ? 0 : buf + 1;
        lbuf = (lbuf == GSTAGES - 1) ? 0 : lbuf + 1;
    }

    // ---- epilogue: lrelu + store (fp32) ----
#pragma unroll
    for (int mt = 0; mt < 4; mt++) {
        int mrow = bm + wm * 64 + mt * 16 + g;
#pragma unroll
        for (int nt = 0; nt < 4; nt++) {
            int ncol = bn + wn * 32 + nt * 8 + t * 2;
            float2 lo, hi;
            lo.x = lrelu(acc[mt][nt][0]);
            lo.y = lrelu(acc[mt][nt][1]);
            hi.x = lrelu(acc[mt][nt][2]);
            hi.y = lrelu(acc[mt][nt][3]);
            *reinterpret_cast<float2*>(C + (size_t)mrow * FOUT + ncol)       = lo;
            *reinterpret_cast<float2*>(C + (size_t)(mrow + 8) * FOUT + ncol) = hi;
        }
    }
}

// ---------------- kernel 3: GAT softmax epilogue (9 warps, 1 dot per warp) ----------------
__global__ void gat_epilogue_kernel(const float* __restrict__ srcz,
                                    const float* __restrict__ hz,
                                    const float* __restrict__ a_attn,
                                    float*       __restrict__ msg)
{
    int n   = blockIdx.x;
    int tid = threadIdx.x;  // 288 = 9 warps
    int warp = tid >> 5, lane = tid & 31;

    __shared__ float zs[RR][FOUT];
    __shared__ float hzs[FOUT];
    __shared__ float scoresm[9];
    __shared__ float alpha[RR];

    const float4* zp4 = reinterpret_cast<const float4*>(srcz + (size_t)n * RR * FOUT);
    float4* zs4 = reinterpret_cast<float4*>(&zs[0][0]);
    for (int i = tid; i < RR * FOUT / 4; i += 288) zs4[i] = zp4[i];
    const float4* hp4 = reinterpret_cast<const float4*>(hz + (size_t)n * FOUT);
    float4* hzs4 = reinterpret_cast<float4*>(hzs);
    for (int i = tid; i < FOUT / 4; i += 288) hzs4[i] = hp4[i];
    __syncthreads();

    {
        const float4* src4 = (warp < 8) ? reinterpret_cast<const float4*>(&zs[warp][0])
                                        : reinterpret_cast<const float4*>(hzs);
        const float4* a4 = reinterpret_cast<const float4*>(a_attn + (warp < 8 ? 0 : FOUT));
        float s = 0.0f;
#pragma unroll
        for (int c = 0; c < 4; c++) {
            float4 z4 = src4[lane + c * 32];
            float4 av = a4[lane + c * 32];
            s += z4.x * av.x + z4.y * av.y + z4.z * av.z + z4.w * av.w;
        }
#pragma unroll
        for (int off = 16; off; off >>= 1)
            s += __shfl_down_sync(0xffffffffu, s, off);
        if (lane == 0) scoresm[warp] = s;
    }
    __syncthreads();

    if (tid == 0) {
        float sh = scoresm[8];
        float sc[RR], mx = -3.402823466e38f;
#pragma unroll
        for (int r = 0; r < RR; r++) {
            sc[r] = lrelu(scoresm[r] + sh);
            mx = fmaxf(mx, sc[r]);
        }
        float sum = 0.0f;
#pragma unroll
        for (int r = 0; r < RR; r++) {
            float e = expf(sc[r] - mx);
            alpha[r] = e;
            sum += e;
        }
        float inv = 1.0f / sum;
#pragma unroll
        for (int r = 0; r < RR; r++) alpha[r] *= inv;
    }
    __syncthreads();

    float al[RR];
#pragma unroll
    for (int r = 0; r < RR; r++) al[r] = alpha[r];

    for (int f = tid; f < FOUT; f += 288) {
        float acc = RESIDUAL * hzs[f];
#pragma unroll
        for (int r = 0; r < RR; r++) acc += al[r] * zs[r][f];
        msg[(size_t)n * FOUT + f] = acc;
    }
}

// ---------------- kernel 4: multi-attention + BatchNorm ----------------
__global__ void final_kernel(const float* __restrict__ Wp1,
                             const float* __restrict__ bp1,
                             const float* __restrict__ Wp2,
                             const float* __restrict__ bp2,
                             const float* __restrict__ gamma,
                             const float* __restrict__ betaBN,
                             const float* __restrict__ mean,
                             const float* __restrict__ var,
                             float*       __restrict__ out)
{
    int n   = blockIdx.x;
    int tid = threadIdx.x;  // 128

    __shared__ float z[2][FOUT];
    __shared__ float wred[4];
    __shared__ float betasm[2];

    for (int f = tid; f < FOUT; f += 128) {
        z[0][f] = g_msg[(size_t)n * FOUT + f];
        z[1][f] = g_msg[(size_t)NN * FOUT + (size_t)n * FOUT + f];
    }
    __syncthreads();

    int i  = tid >> 6;
    int hd = tid & 63;
    float acc = 0.0f;
#pragma unroll 8
    for (int k = 0; k < FOUT; k++) acc += z[i][k] * Wp1[k * HIDD + hd];
    float t  = tanhf(acc + bp1[hd]);
    float pw = t * Wp2[hd];

#pragma unroll
    for (int off = 16; off; off >>= 1)
        pw += __shfl_down_sync(0xffffffffu, pw, off);
    if ((tid & 31) == 0) wred[tid >> 5] = pw;
    __syncthreads();
    if (tid == 0) {
        float w0 = tanhf(wred[0] + wred[1] + bp2[0]);
        float w1 = tanhf(wred[2] + wred[3] + bp2[0]);
        float m  = fmaxf(w0, w1);
        float e0 = expf(w0 - m), e1 = expf(w1 - m);
        float inv = 1.0f / (e0 + e1);
        betasm[0] = e0 * inv;
        betasm[1] = e1 * inv;
    }
    __syncthreads();

    float b0 = betasm[0], b1 = betasm[1];
    for (int f = tid; f < FOUT; f += 128) {
        float v = b0 * z[0][f] + b1 * z[1][f];
        out[(size_t)n * FOUT + f] =
            (v - mean[f]) * rsqrtf(var[f] + BN_EPS) * gamma[f] + betaBN[f];
    }
}

// ---------------- launch ----------------
extern "C" void kernel_launch(void* const* d_in, const int* in_sizes, int n_in,
                              void* d_out, int out_size)
{
    const float* src_h     = (const float*)d_in[0];
    const float* src_h_img = (const float*)d_in[1];
    const int*   rel       = (const int*)  d_in[2];
    const float* h         = (const float*)d_in[3];
    const float* h_img     = (const float*)d_in[4];
    const float* W0        = (const float*)d_in[5];
    const float* a0        = (const float*)d_in[6];
    const float* W1        = (const float*)d_in[7];
    const float* a1        = (const float*)d_in[8];
    const float* Wp1       = (const float*)d_in[9];
    const float* bp1       = (const float*)d_in[10];
    const float* Wp2       = (const float*)d_in[11];
    const float* bp2       = (const float*)d_in[12];
    const float* gamma     = (const float*)d_in[13];
    const float* betaBN    = (const float*)d_in[14];
    const float* mean      = (const float*)d_in[15];
    const float* var       = (const float*)d_in[16];
    float* out = (float*)d_out;

    __half *att, *wt, *hconv;
    float *srcz, *hz, *msg;
    cudaGetSymbolAddress((void**)&att,   g_att);
    cudaGetSymbolAddress((void**)&srcz,  g_srcz);
    cudaGetSymbolAddress((void**)&hz,    g_hz);
    cudaGetSymbolAddress((void**)&msg,   g_msg);
    cudaGetSymbolAddress((void**)&wt,    g_wt);
    cudaGetSymbolAddress((void**)&hconv, g_hconv);

    static cudaStream_t s1 = nullptr;
    static cudaEvent_t eFork = nullptr, eJoin = nullptr;
    if (!s1) {
        cudaStreamCreateWithFlags(&s1, cudaStreamNonBlocking);
        cudaEventCreateWithFlags(&eFork, cudaEventDisableTiming);
        cudaEventCreateWithFlags(&eJoin, cudaEventDisableTiming);
        cudaFuncSetAttribute(gemm_tc_kernel,
                             cudaFuncAttributeMaxDynamicSharedMemorySize, GEMM_SMEM);
    }

    const float* srcs[2] = {src_h, src_h_img};
    const float* hs[2]   = {h, h_img};
    const float* Ws[2]   = {W0, W1};
    const float* as[2]   = {a0, a1};

    // fork: pass 1 runs on s1 concurrently with pass 0 on stream 0
    cudaEventRecord(eFork, 0);
    cudaStreamWaitEvent(s1, eFork, 0);

    for (int pass = 0; pass < 2; pass++) {
        cudaStream_t st = pass ? s1 : (cudaStream_t)0;
        __half* attP   = att   + (size_t)pass * NN * RR * FIN;
        __half* wtP    = wt    + (size_t)pass * FIN * FOUT;
        __half* hconvP = hconv + (size_t)pass * NN * FIN;
        float*  srczP  = srcz  + (size_t)pass * NN * RR * FOUT;
        float*  hzP    = hz    + (size_t)pass * NN * FOUT;

        transposeW_kernel<<<dim3(16, 16), dim3(32, 32), 0, st>>>(Ws[pass], wtP);
        convert_kernel<<<(NN * FIN / 4 + 255) / 256, 256, 0, st>>>(hs[pass], hconvP, NN * FIN / 4);
        maxpool_kernel<<<NN, 128, 0, st>>>(srcs[pass], rel, attP);
        gemm_tc_kernel<<<dim3(FOUT / 128, MBBIG + NN / 128), 256, GEMM_SMEM, st>>>(
            attP, hconvP, wtP, srczP, hzP);
        gat_epilogue_kernel<<<NN, 288, 0, st>>>(srczP, hzP, as[pass],
                                                msg + (size_t)pass * NN * FOUT);
    }

    // join: final_kernel needs both passes' msg
    cudaEventRecord(eJoin, s1);
    cudaStreamWaitEvent((cudaStream_t)0, eJoin, 0);
    final_kernel<<<NN, 128>>>(Wp1, bp1, Wp2, bp2, gamma, betaBN, mean, var, out);
}

// round 10
// speedup vs baseline: 1.6074x; 1.0750x over previous
#include <cuda_runtime.h>
#include <cuda_fp16.h>
#include <math.h>
#include <cstdint>

#define NN   16384
#define DD   16
#define FIN  512
#define FOUT 512
#define RR   8
#define HIDD 64
#define BN_EPS 1e-5f
#define RESIDUAL 0.12f

// ---------------- scratch (device globals: allocation-free), per-pass ----------------
__device__ __half g_att  [2ull * NN * RR * FIN];    // 268 MB (fp16)
__device__ __half g_srcz [2ull * NN * RR * FOUT];   // 268 MB (fp16)
__device__ __half g_hz   [2ull * NN * FOUT];        // 33 MB (fp16)
__device__ float  g_msg  [2ull * NN * FOUT];        // 67 MB
__device__ __half g_wt   [2ull * FIN * FOUT];       // 1 MB
__device__ __half g_hconv[2ull * NN * FIN];         // 34 MB

__device__ __forceinline__ float lrelu(float x) { return x >= 0.0f ? x : 0.2f * x; }

__device__ __forceinline__ uint32_t smem_u32(const void* p) {
    uint32_t a;
    asm("{ .reg .u64 t; cvta.to.shared.u64 t, %1; cvt.u32.u64 %0, t; }" : "=r"(a) : "l"(p));
    return a;
}
__device__ __forceinline__ void cp_async16(uint32_t dst, const void* src) {
    asm volatile("cp.async.cg.shared.global [%0], [%1], 16;" :: "r"(dst), "l"(src));
}
#define CP_COMMIT() asm volatile("cp.async.commit_group;" ::: "memory")
#define CP_WAIT(n)  asm volatile("cp.async.wait_group %0;" :: "n"(n) : "memory")

__device__ __forceinline__ void ldsm_x4(uint32_t* r, uint32_t addr) {
    asm volatile("ldmatrix.sync.aligned.m8n8.x4.shared.b16 {%0,%1,%2,%3}, [%4];"
        : "=r"(r[0]), "=r"(r[1]), "=r"(r[2]), "=r"(r[3]) : "r"(addr));
}

__device__ __forceinline__ void mma_f16(float& c0, float& c1, float& c2, float& c3,
                                        uint32_t a0, uint32_t a1, uint32_t a2, uint32_t a3,
                                        uint32_t b0, uint32_t b1) {
    asm volatile(
        "mma.sync.aligned.m16n8k16.row.col.f32.f16.f16.f32 "
        "{%0,%1,%2,%3}, {%4,%5,%6,%7}, {%8,%9}, {%0,%1,%2,%3};"
        : "+f"(c0), "+f"(c1), "+f"(c2), "+f"(c3)
        : "r"(a0), "r"(a1), "r"(a2), "r"(a3), "r"(b0), "r"(b1));
}

// ---------------- kernel 0a: transpose W [K,N] -> WT [N,K], fp16 ----------------
__global__ void transposeW_kernel(const float* __restrict__ W, __half* __restrict__ WT)
{
    __shared__ float t[32][33];
    int bx = blockIdx.x * 32, by = blockIdx.y * 32;
    t[threadIdx.y][threadIdx.x] = W[(by + threadIdx.y) * FOUT + bx + threadIdx.x];
    __syncthreads();
    WT[(bx + threadIdx.y) * FIN + by + threadIdx.x] = __float2half_rn(t[threadIdx.x][threadIdx.y]);
}

// ---------------- kernel 0b: convert h to fp16 ----------------
__global__ void convert_kernel(const float* __restrict__ in, __half* __restrict__ out, int n4)
{
    int i = blockIdx.x * blockDim.x + threadIdx.x;
    if (i < n4) {
        float4 v = reinterpret_cast<const float4*>(in)[i];
        __half2 h0 = __floats2half2_rn(v.x, v.y);
        __half2 h1 = __floats2half2_rn(v.z, v.w);
        uint2 st;
        st.x = *reinterpret_cast<uint32_t*>(&h0);
        st.y = *reinterpret_cast<uint32_t*>(&h1);
        reinterpret_cast<uint2*>(out)[i] = st;
    }
}

// ---------------- kernel 1: relation maxpool (fp16 output) ----------------
__global__ void maxpool_kernel(const float* __restrict__ src,
                               const int*   __restrict__ rel,
                               __half*      __restrict__ att)
{
    int n   = blockIdx.x;
    int tid = threadIdx.x;  // 128

    __shared__ int rl[DD];
    __shared__ int cnt[RR];
    if (tid < RR) cnt[tid] = 0;
    __syncthreads();
    if (tid < DD) {
        int r = rel[n * DD + tid];
        rl[tid] = r;
        atomicAdd(&cnt[r], 1);
    }
    __syncthreads();

    const float4* sp = reinterpret_cast<const float4*>(src + (size_t)n * DD * FIN);
    const float NEG = -3.402823466e38f;

    float4 mx[RR];
#pragma unroll
    for (int r = 0; r < RR; r++) mx[r] = make_float4(NEG, NEG, NEG, NEG);

#pragma unroll
    for (int d = 0; d < DD; d++) {
        float4 v = sp[d * (FIN / 4) + tid];
        int rd = rl[d];
#pragma unroll
        for (int r = 0; r < RR; r++) {
            bool m = (rd == r);
            mx[r].x = m ? fmaxf(mx[r].x, v.x) : mx[r].x;
            mx[r].y = m ? fmaxf(mx[r].y, v.y) : mx[r].y;
            mx[r].z = m ? fmaxf(mx[r].z, v.z) : mx[r].z;
            mx[r].w = m ? fmaxf(mx[r].w, v.w) : mx[r].w;
        }
    }

    uint2* ap = reinterpret_cast<uint2*>(att + (size_t)n * RR * FIN);
#pragma unroll
    for (int r = 0; r < RR; r++) {
        float4 o = mx[r];
        if (cnt[r] != DD) {
            o.x = fmaxf(o.x, 0.0f);
            o.y = fmaxf(o.y, 0.0f);
            o.z = fmaxf(o.z, 0.0f);
            o.w = fmaxf(o.w, 0.0f);
        }
        __half2 h0 = __floats2half2_rn(o.x, o.y);
        __half2 h1 = __floats2half2_rn(o.z, o.w);
        uint2 st;
        st.x = *reinterpret_cast<uint32_t*>(&h0);
        st.y = *reinterpret_cast<uint32_t*>(&h1);
        ap[r * (FIN / 4) + tid] = st;
    }
}

// ---------------- kernel 2: mma.sync fp16 GEMM with ldmatrix fragments ----------------
// Fused: blocks y<1024 compute srcz = lrelu(att @ WT^T); y>=1024 compute hz from hconv.
// BM=128, BN=128, BK=64 (halfs). 256 threads, 8 warps (2M x 4N), warp tile 64x32.
// 3-stage cp.async ring; fp16 output.
#define TSH 72
#define STAGE_HALFS ((128 + 128) * TSH)
#define GSTAGES 3
#define GEMM_SMEM (GSTAGES * STAGE_HALFS * 2)    // 110592 bytes
#define MBBIG (NN * RR / 128)

__global__ void __launch_bounds__(256, 2)
gemm_tc_kernel(const __half* __restrict__ Abig,
               const __half* __restrict__ Asmall,
               const __half* __restrict__ Bt,
               __half*       __restrict__ Cbig,
               __half*       __restrict__ Csmall)
{
    extern __shared__ __half smh[];
    int tid  = threadIdx.x;
    int wid  = tid >> 5;
    int lane = tid & 31;
    int wm   = wid & 1;
    int wn   = wid >> 1;
    int g    = lane >> 2;
    int t    = lane & 3;
    int q    = lane >> 3;
    int lr   = lane & 7;

    int mb = blockIdx.y;
    const __half* A;
    __half* C;
    int bm;
    if (mb < MBBIG) { A = Abig;   C = Cbig;   bm = mb * 128; }
    else            { A = Asmall; C = Csmall; bm = (mb - MBBIG) * 128; }
    int bn = blockIdx.x * 128;

    int row0 = tid >> 3;
    int kc0  = (tid & 7) * 8;
    const __half* Ag = A  + (size_t)(bm + row0) * FIN + kc0;
    const __half* Bg = Bt + (size_t)(bn + row0) * FIN + kc0;

    uint32_t sbase = smem_u32(smh);
    uint32_t dA = sbase + (uint32_t)(row0 * TSH + kc0) * 2;
    uint32_t dB = sbase + (uint32_t)((128 + row0) * TSH + kc0) * 2;
    const uint32_t stageB  = STAGE_HALFS * 2;
    const uint32_t rowblkB = (uint32_t)(32 * TSH) * 2;
    const size_t   rowblkG = (size_t)32 * FIN;

    uint32_t laneAoff = (uint32_t)((wm * 64 + (q & 1) * 8 + lr) * TSH + (q >> 1) * 8) * 2;
    uint32_t laneBoff = (uint32_t)((128 + wn * 32 + (q >> 1) * 8 + lr) * TSH + (q & 1) * 8) * 2;

    float acc[4][4][4];
#pragma unroll
    for (int i = 0; i < 4; i++)
#pragma unroll
        for (int j = 0; j < 4; j++)
#pragma unroll
            for (int x = 0; x < 4; x++) acc[i][j][x] = 0.0f;

    const int NK = FIN / 64;  // 8 stages

#pragma unroll
    for (int s = 0; s < GSTAGES - 1; s++) {
        int k0 = s * 64;
        uint32_t so = s * stageB;
#pragma unroll
        for (int j = 0; j < 4; j++) {
            cp_async16(dA + so + j * rowblkB, Ag + j * rowblkG + k0);
            cp_async16(dB + so + j * rowblkB, Bg + j * rowblkG + k0);
        }
        CP_COMMIT();
    }
    CP_WAIT(GSTAGES - 2);

    int buf = 0, lbuf = GSTAGES - 1;
    for (int i = 0; i < NK; i++) {
        __syncthreads();

        if (i + GSTAGES - 1 < NK) {
            int k0 = (i + GSTAGES - 1) * 64;
            uint32_t so = lbuf * stageB;
#pragma unroll
            for (int j = 0; j < 4; j++) {
                cp_async16(dA + so + j * rowblkB, Ag + j * rowblkG + k0);
                cp_async16(dB + so + j * rowblkB, Bg + j * rowblkG + k0);
            }
        }
        CP_COMMIT();

        uint32_t sa = sbase + buf * stageB;
        uint32_t aA = sa + laneAoff;
        uint32_t aB = sa + laneBoff;
#pragma unroll
        for (int kk = 0; kk < 4; kk++) {
            uint32_t a[4][4];
            uint32_t b[2][4];
#pragma unroll
            for (int mt = 0; mt < 4; mt++)
                ldsm_x4(a[mt], aA + (uint32_t)(mt * 16 * TSH + kk * 16) * 2);
#pragma unroll
            for (int n2 = 0; n2 < 2; n2++)
                ldsm_x4(b[n2], aB + (uint32_t)(n2 * 16 * TSH + kk * 16) * 2);
#pragma unroll
            for (int mt = 0; mt < 4; mt++)
#pragma unroll
                for (int nt = 0; nt < 4; nt++)
                    mma_f16(acc[mt][nt][0], acc[mt][nt][1], acc[mt][nt][2], acc[mt][nt][3],
                            a[mt][0], a[mt][1], a[mt][2], a[mt][3],
                            b[nt >> 1][(nt & 1) * 2], b[nt >> 1][(nt & 1) * 2 + 1]);
        }

        CP_WAIT(GSTAGES - 2);
        buf  = (buf  == GSTAGES - 1) ? 0 : buf + 1;
        lbuf = (lbuf == GSTAGES - 1) ? 0 : lbuf + 1;
    }

    // ---- epilogue: lrelu + fp16 store ----
#pragma unroll
    for (int mt = 0; mt < 4; mt++) {
        int mrow = bm + wm * 64 + mt * 16 + g;
#pragma unroll
        for (int nt = 0; nt < 4; nt++) {
            int ncol = bn + wn * 32 + nt * 8 + t * 2;
            __half2 lo = __floats2half2_rn(lrelu(acc[mt][nt][0]), lrelu(acc[mt][nt][1]));
            __half2 hi = __floats2half2_rn(lrelu(acc[mt][nt][2]), lrelu(acc[mt][nt][3]));
            *reinterpret_cast<__half2*>(C + (size_t)mrow * FOUT + ncol)       = lo;
            *reinterpret_cast<__half2*>(C + (size_t)(mrow + 8) * FOUT + ncol) = hi;
        }
    }
}

// ---------------- kernel 3: GAT softmax epilogue (fp16 inputs) ----------------
__global__ void gat_epilogue_kernel(const __half* __restrict__ srcz,
                                    const __half* __restrict__ hz,
                                    const float*  __restrict__ a_attn,
                                    float*        __restrict__ msg)
{
    int n   = blockIdx.x;
    int tid = threadIdx.x;  // 288 = 9 warps
    int warp = tid >> 5, lane = tid & 31;

    __shared__ __half zs[RR][FOUT];   // 8 KB
    __shared__ __half hzs[FOUT];      // 1 KB
    __shared__ float scoresm[9];
    __shared__ float alpha[RR];

    // load: RR*FOUT halfs = 512 uint4 chunks; FOUT = 64 chunks
    const uint4* zp = reinterpret_cast<const uint4*>(srcz + (size_t)n * RR * FOUT);
    uint4* zsm = reinterpret_cast<uint4*>(&zs[0][0]);
    for (int i = tid; i < RR * FOUT / 8; i += 288) zsm[i] = zp[i];
    const uint4* hp = reinterpret_cast<const uint4*>(hz + (size_t)n * FOUT);
    uint4* hsm = reinterpret_cast<uint4*>(hzs);
    for (int i = tid; i < FOUT / 8; i += 288) hsm[i] = hp[i];
    __syncthreads();

    // warp w (0..7): dot(zs[w], a[:512]); warp 8: dot(hzs, a[512:])
    {
        const __half* src = (warp < 8) ? &zs[warp][0] : hzs;
        const float* av = a_attn + (warp < 8 ? 0 : FOUT);
        float s = 0.0f;
#pragma unroll
        for (int c = 0; c < 2; c++) {
            int base = (lane + c * 32) * 8;  // 8 halfs per lane-chunk
            uint4 hv = *reinterpret_cast<const uint4*>(src + base);
            const __half2* hp2 = reinterpret_cast<const __half2*>(&hv);
            const float4* a4 = reinterpret_cast<const float4*>(av + base);
            float4 a0 = a4[0], a1 = a4[1];
            float2 z0 = __half22float2(hp2[0]);
            float2 z1 = __half22float2(hp2[1]);
            float2 z2 = __half22float2(hp2[2]);
            float2 z3 = __half22float2(hp2[3]);
            s += z0.x * a0.x + z0.y * a0.y + z1.x * a0.z + z1.y * a0.w;
            s += z2.x * a1.x + z2.y * a1.y + z3.x * a1.z + z3.y * a1.w;
        }
#pragma unroll
        for (int off = 16; off; off >>= 1)
            s += __shfl_down_sync(0xffffffffu, s, off);
        if (lane == 0) scoresm[warp] = s;
    }
    __syncthreads();

    if (tid == 0) {
        float sh = scoresm[8];
        float sc[RR], mx = -3.402823466e38f;
#pragma unroll
        for (int r = 0; r < RR; r++) {
            sc[r] = lrelu(scoresm[r] + sh);
            mx = fmaxf(mx, sc[r]);
        }
        float sum = 0.0f;
#pragma unroll
        for (int r = 0; r < RR; r++) {
            float e = expf(sc[r] - mx);
            alpha[r] = e;
            sum += e;
        }
        float inv = 1.0f / sum;
#pragma unroll
        for (int r = 0; r < RR; r++) alpha[r] *= inv;
    }
    __syncthreads();

    float al[RR];
#pragma unroll
    for (int r = 0; r < RR; r++) al[r] = alpha[r];

    for (int f = tid; f < FOUT; f += 288) {
        float acc = RESIDUAL * __half2float(hzs[f]);
#pragma unroll
        for (int r = 0; r < RR; r++) acc += al[r] * __half2float(zs[r][f]);
        msg[(size_t)n * FOUT + f] = acc;
    }
}

// ---------------- kernel 4: multi-attention + BatchNorm ----------------
__global__ void final_kernel(const float* __restrict__ Wp1,
                             const float* __restrict__ bp1,
                             const float* __restrict__ Wp2,
                             const float* __restrict__ bp2,
                             const float* __restrict__ gamma,
                             const float* __restrict__ betaBN,
                             const float* __restrict__ mean,
                             const float* __restrict__ var,
                             float*       __restrict__ out)
{
    int n   = blockIdx.x;
    int tid = threadIdx.x;  // 128

    __shared__ float z[2][FOUT];
    __shared__ float wred[4];
    __shared__ float betasm[2];

    for (int f = tid; f < FOUT; f += 128) {
        z[0][f] = g_msg[(size_t)n * FOUT + f];
        z[1][f] = g_msg[(size_t)NN * FOUT + (size_t)n * FOUT + f];
    }
    __syncthreads();

    int i  = tid >> 6;
    int hd = tid & 63;
    float acc = 0.0f;
#pragma unroll 8
    for (int k = 0; k < FOUT; k++) acc += z[i][k] * Wp1[k * HIDD + hd];
    float t  = tanhf(acc + bp1[hd]);
    float pw = t * Wp2[hd];

#pragma unroll
    for (int off = 16; off; off >>= 1)
        pw += __shfl_down_sync(0xffffffffu, pw, off);
    if ((tid & 31) == 0) wred[tid >> 5] = pw;
    __syncthreads();
    if (tid == 0) {
        float w0 = tanhf(wred[0] + wred[1] + bp2[0]);
        float w1 = tanhf(wred[2] + wred[3] + bp2[0]);
        float m  = fmaxf(w0, w1);
        float e0 = expf(w0 - m), e1 = expf(w1 - m);
        float inv = 1.0f / (e0 + e1);
        betasm[0] = e0 * inv;
        betasm[1] = e1 * inv;
    }
    __syncthreads();

    float b0 = betasm[0], b1 = betasm[1];
    for (int f = tid; f < FOUT; f += 128) {
        float v = b0 * z[0][f] + b1 * z[1][f];
        out[(size_t)n * FOUT + f] =
            (v - mean[f]) * rsqrtf(var[f] + BN_EPS) * gamma[f] + betaBN[f];
    }
}

// ---------------- launch ----------------
extern "C" void kernel_launch(void* const* d_in, const int* in_sizes, int n_in,
                              void* d_out, int out_size)
{
    const float* src_h     = (const float*)d_in[0];
    const float* src_h_img = (const float*)d_in[1];
    const int*   rel       = (const int*)  d_in[2];
    const float* h         = (const float*)d_in[3];
    const float* h_img     = (const float*)d_in[4];
    const float* W0        = (const float*)d_in[5];
    const float* a0        = (const float*)d_in[6];
    const float* W1        = (const float*)d_in[7];
    const float* a1        = (const float*)d_in[8];
    const float* Wp1       = (const float*)d_in[9];
    const float* bp1       = (const float*)d_in[10];
    const float* Wp2       = (const float*)d_in[11];
    const float* bp2       = (const float*)d_in[12];
    const float* gamma     = (const float*)d_in[13];
    const float* betaBN    = (const float*)d_in[14];
    const float* mean      = (const float*)d_in[15];
    const float* var       = (const float*)d_in[16];
    float* out = (float*)d_out;

    __half *att, *wt, *hconv, *srcz, *hz;
    float *msg;
    cudaGetSymbolAddress((void**)&att,   g_att);
    cudaGetSymbolAddress((void**)&srcz,  g_srcz);
    cudaGetSymbolAddress((void**)&hz,    g_hz);
    cudaGetSymbolAddress((void**)&msg,   g_msg);
    cudaGetSymbolAddress((void**)&wt,    g_wt);
    cudaGetSymbolAddress((void**)&hconv, g_hconv);

    static cudaStream_t s1 = nullptr;
    static cudaEvent_t eFork = nullptr, eJoin = nullptr;
    if (!s1) {
        cudaStreamCreateWithFlags(&s1, cudaStreamNonBlocking);
        cudaEventCreateWithFlags(&eFork, cudaEventDisableTiming);
        cudaEventCreateWithFlags(&eJoin, cudaEventDisableTiming);
        cudaFuncSetAttribute(gemm_tc_kernel,
                             cudaFuncAttributeMaxDynamicSharedMemorySize, GEMM_SMEM);
    }

    const float* srcs[2] = {src_h, src_h_img};
    const float* hs[2]   = {h, h_img};
    const float* Ws[2]   = {W0, W1};
    const float* as[2]   = {a0, a1};

    cudaEventRecord(eFork, 0);
    cudaStreamWaitEvent(s1, eFork, 0);

    for (int pass = 0; pass < 2; pass++) {
        cudaStream_t st = pass ? s1 : (cudaStream_t)0;
        __half* attP   = att   + (size_t)pass * NN * RR * FIN;
        __half* wtP    = wt    + (size_t)pass * FIN * FOUT;
        __half* hconvP = hconv + (size_t)pass * NN * FIN;
        __half* srczP  = srcz  + (size_t)pass * NN * RR * FOUT;
        __half* hzP    = hz    + (size_t)pass * NN * FOUT;

        transposeW_kernel<<<dim3(16, 16), dim3(32, 32), 0, st>>>(Ws[pass], wtP);
        convert_kernel<<<(NN * FIN / 4 + 255) / 256, 256, 0, st>>>(hs[pass], hconvP, NN * FIN / 4);
        maxpool_kernel<<<NN, 128, 0, st>>>(srcs[pass], rel, attP);
        gemm_tc_kernel<<<dim3(FOUT / 128, MBBIG + NN / 128), 256, GEMM_SMEM, st>>>(
            attP, hconvP, wtP, srczP, hzP);
        gat_epilogue_kernel<<<NN, 288, 0, st>>>(srczP, hzP, as[pass],
                                                msg + (size_t)pass * NN * FOUT);
    }

    cudaEventRecord(eJoin, s1);
    cudaStreamWaitEvent((cudaStream_t)0, eJoin, 0);
    final_kernel<<<NN, 128>>>(Wp1, bp1, Wp2, bp2, gamma, betaBN, mean, var, out);
}

// round 11
// speedup vs baseline: 1.6251x; 1.0110x over previous
#include <cuda_runtime.h>
#include <cuda_fp16.h>
#include <math.h>
#include <cstdint>

#define NN   16384
#define DD   16
#define FIN  512
#define FOUT 512
#define RR   8
#define HIDD 64
#define BN_EPS 1e-5f
#define RESIDUAL 0.12f

// ---------------- scratch (device globals: allocation-free), per-pass ----------------
__device__ __half g_att  [2ull * NN * RR * FIN];    // 268 MB (fp16)
__device__ __half g_srcz [2ull * NN * RR * FOUT];   // 268 MB (fp16)
__device__ __half g_hz   [2ull * NN * FOUT];        // 33 MB (fp16)
__device__ float  g_msg  [2ull * NN * FOUT];        // 67 MB
__device__ __half g_wt   [2ull * FIN * FOUT];       // 1 MB
__device__ __half g_hconv[2ull * NN * FIN];         // 34 MB

__device__ __forceinline__ float lrelu(float x) { return x >= 0.0f ? x : 0.2f * x; }

__device__ __forceinline__ uint32_t smem_u32(const void* p) {
    uint32_t a;
    asm("{ .reg .u64 t; cvta.to.shared.u64 t, %1; cvt.u32.u64 %0, t; }" : "=r"(a) : "l"(p));
    return a;
}
__device__ __forceinline__ void cp_async16(uint32_t dst, const void* src) {
    asm volatile("cp.async.cg.shared.global [%0], [%1], 16;" :: "r"(dst), "l"(src));
}
#define CP_COMMIT() asm volatile("cp.async.commit_group;" ::: "memory")
#define CP_WAIT(n)  asm volatile("cp.async.wait_group %0;" :: "n"(n) : "memory")

__device__ __forceinline__ void ldsm_x4(uint32_t* r, uint32_t addr) {
    asm volatile("ldmatrix.sync.aligned.m8n8.x4.shared.b16 {%0,%1,%2,%3}, [%4];"
        : "=r"(r[0]), "=r"(r[1]), "=r"(r[2]), "=r"(r[3]) : "r"(addr));
}

__device__ __forceinline__ void mma_f16(float& c0, float& c1, float& c2, float& c3,
                                        uint32_t a0, uint32_t a1, uint32_t a2, uint32_t a3,
                                        uint32_t b0, uint32_t b1) {
    asm volatile(
        "mma.sync.aligned.m16n8k16.row.col.f32.f16.f16.f32 "
        "{%0,%1,%2,%3}, {%4,%5,%6,%7}, {%8,%9}, {%0,%1,%2,%3};"
        : "+f"(c0), "+f"(c1), "+f"(c2), "+f"(c3)
        : "r"(a0), "r"(a1), "r"(a2), "r"(a3), "r"(b0), "r"(b1));
}

// ---------------- kernel 0a: transpose W [K,N] -> WT [N,K], fp16 ----------------
__global__ void transposeW_kernel(const float* __restrict__ W, __half* __restrict__ WT)
{
    __shared__ float t[32][33];
    int bx = blockIdx.x * 32, by = blockIdx.y * 32;
    t[threadIdx.y][threadIdx.x] = W[(by + threadIdx.y) * FOUT + bx + threadIdx.x];
    __syncthreads();
    WT[(bx + threadIdx.y) * FIN + by + threadIdx.x] = __float2half_rn(t[threadIdx.x][threadIdx.y]);
}

// ---------------- kernel 0b: convert h to fp16 ----------------
__global__ void convert_kernel(const float* __restrict__ in, __half* __restrict__ out, int n4)
{
    int i = blockIdx.x * blockDim.x + threadIdx.x;
    if (i < n4) {
        float4 v = reinterpret_cast<const float4*>(in)[i];
        __half2 h0 = __floats2half2_rn(v.x, v.y);
        __half2 h1 = __floats2half2_rn(v.z, v.w);
        uint2 st;
        st.x = *reinterpret_cast<uint32_t*>(&h0);
        st.y = *reinterpret_cast<uint32_t*>(&h1);
        reinterpret_cast<uint2*>(out)[i] = st;
    }
}

// ---------------- kernel 1: relation maxpool (fp16 output) ----------------
__global__ void maxpool_kernel(const float* __restrict__ src,
                               const int*   __restrict__ rel,
                               __half*      __restrict__ att)
{
    int n   = blockIdx.x;
    int tid = threadIdx.x;  // 128

    __shared__ int rl[DD];
    __shared__ int cnt[RR];
    if (tid < RR) cnt[tid] = 0;
    __syncthreads();
    if (tid < DD) {
        int r = rel[n * DD + tid];
        rl[tid] = r;
        atomicAdd(&cnt[r], 1);
    }
    __syncthreads();

    const float4* sp = reinterpret_cast<const float4*>(src + (size_t)n * DD * FIN);
    const float NEG = -3.402823466e38f;

    float4 mx[RR];
#pragma unroll
    for (int r = 0; r < RR; r++) mx[r] = make_float4(NEG, NEG, NEG, NEG);

#pragma unroll
    for (int d = 0; d < DD; d++) {
        float4 v = sp[d * (FIN / 4) + tid];
        int rd = rl[d];
#pragma unroll
        for (int r = 0; r < RR; r++) {
            bool m = (rd == r);
            mx[r].x = m ? fmaxf(mx[r].x, v.x) : mx[r].x;
            mx[r].y = m ? fmaxf(mx[r].y, v.y) : mx[r].y;
            mx[r].z = m ? fmaxf(mx[r].z, v.z) : mx[r].z;
            mx[r].w = m ? fmaxf(mx[r].w, v.w) : mx[r].w;
        }
    }

    uint2* ap = reinterpret_cast<uint2*>(att + (size_t)n * RR * FIN);
#pragma unroll
    for (int r = 0; r < RR; r++) {
        float4 o = mx[r];
        if (cnt[r] != DD) {
            o.x = fmaxf(o.x, 0.0f);
            o.y = fmaxf(o.y, 0.0f);
            o.z = fmaxf(o.z, 0.0f);
            o.w = fmaxf(o.w, 0.0f);
        }
        __half2 h0 = __floats2half2_rn(o.x, o.y);
        __half2 h1 = __floats2half2_rn(o.z, o.w);
        uint2 st;
        st.x = *reinterpret_cast<uint32_t*>(&h0);
        st.y = *reinterpret_cast<uint32_t*>(&h1);
        ap[r * (FIN / 4) + tid] = st;
    }
}

// ---------------- kernel 2: mma.sync fp16 GEMM with ldmatrix fragments ----------------
// Fused: blocks y<1024 compute srcz = lrelu(att @ WT^T); y>=1024 compute hz from hconv.
// BM=128, BN=128, BK=64 (halfs). 512 threads, 16 warps (4M x 4N), warp tile 32x32.
// 3-stage cp.async ring; fp16 output. 2 CTAs/SM -> 32 warps/SM for latency hiding.
#define TSH 72
#define STAGE_HALFS ((128 + 128) * TSH)
#define GSTAGES 3
#define GEMM_SMEM (GSTAGES * STAGE_HALFS * 2)    // 110592 bytes
#define MBBIG (NN * RR / 128)

__global__ void __launch_bounds__(512, 2)
gemm_tc_kernel(const __half* __restrict__ Abig,
               const __half* __restrict__ Asmall,
               const __half* __restrict__ Bt,
               __half*       __restrict__ Cbig,
               __half*       __restrict__ Csmall)
{
    extern __shared__ __half smh[];
    int tid  = threadIdx.x;
    int wid  = tid >> 5;
    int lane = tid & 31;
    int wm   = wid & 3;     // 4 row slabs of 32
    int wn   = wid >> 2;    // 4 col slabs of 32
    int g    = lane >> 2;
    int t    = lane & 3;
    int q    = lane >> 3;   // ldmatrix quadrant 0..3
    int lr   = lane & 7;

    int mb = blockIdx.y;
    const __half* A;
    __half* C;
    int bm;
    if (mb < MBBIG) { A = Abig;   C = Cbig;   bm = mb * 128; }
    else            { A = Asmall; C = Csmall; bm = (mb - MBBIG) * 128; }
    int bn = blockIdx.x * 128;

    // stage copy: A 128 rows + B 128 rows, 64 halfs (128B) per row.
    // 512 threads: row0 = tid>>3 (0..63), each thread does rows {row0, row0+64} x {A,B}.
    int row0 = tid >> 3;
    int kc0  = (tid & 7) * 8;
    const __half* Ag = A  + (size_t)(bm + row0) * FIN + kc0;
    const __half* Bg = Bt + (size_t)(bn + row0) * FIN + kc0;

    uint32_t sbase = smem_u32(smh);
    uint32_t dA = sbase + (uint32_t)(row0 * TSH + kc0) * 2;
    uint32_t dB = sbase + (uint32_t)((128 + row0) * TSH + kc0) * 2;
    const uint32_t stageB  = STAGE_HALFS * 2;
    const uint32_t rowblkB = (uint32_t)(64 * TSH) * 2;   // 64 smem rows
    const size_t   rowblkG = (size_t)64 * FIN;           // 64 gmem rows

    uint32_t laneAoff = (uint32_t)((wm * 32 + (q & 1) * 8 + lr) * TSH + (q >> 1) * 8) * 2;
    uint32_t laneBoff = (uint32_t)((128 + wn * 32 + (q >> 1) * 8 + lr) * TSH + (q & 1) * 8) * 2;

    float acc[2][4][4];
#pragma unroll
    for (int i = 0; i < 2; i++)
#pragma unroll
        for (int j = 0; j < 4; j++)
#pragma unroll
            for (int x = 0; x < 4; x++) acc[i][j][x] = 0.0f;

    const int NK = FIN / 64;  // 8 stages

#pragma unroll
    for (int s = 0; s < GSTAGES - 1; s++) {
        int k0 = s * 64;
        uint32_t so = s * stageB;
#pragma unroll
        for (int j = 0; j < 2; j++) {
            cp_async16(dA + so + j * rowblkB, Ag + j * rowblkG + k0);
            cp_async16(dB + so + j * rowblkB, Bg + j * rowblkG + k0);
        }
        CP_COMMIT();
    }
    CP_WAIT(GSTAGES - 2);

    int buf = 0, lbuf = GSTAGES - 1;
    for (int i = 0; i < NK; i++) {
        __syncthreads();

        if (i + GSTAGES - 1 < NK) {
            int k0 = (i + GSTAGES - 1) * 64;
            uint32_t so = lbuf * stageB;
#pragma unroll
            for (int j = 0; j < 2; j++) {
                cp_async16(dA + so + j * rowblkB, Ag + j * rowblkG + k0);
                cp_async16(dB + so + j * rowblkB, Bg + j * rowblkG + k0);
            }
        }
        CP_COMMIT();

        uint32_t sa = sbase + buf * stageB;
        uint32_t aA = sa + laneAoff;
        uint32_t aB = sa + laneBoff;
#pragma unroll
        for (int kk = 0; kk < 4; kk++) {
            uint32_t a[2][4];
            uint32_t b[2][4];
#pragma unroll
            for (int mt = 0; mt < 2; mt++)
                ldsm_x4(a[mt], aA + (uint32_t)(mt * 16 * TSH + kk * 16) * 2);
#pragma unroll
            for (int n2 = 0; n2 < 2; n2++)
                ldsm_x4(b[n2], aB + (uint32_t)(n2 * 16 * TSH + kk * 16) * 2);
#pragma unroll
            for (int mt = 0; mt < 2; mt++)
#pragma unroll
                for (int nt = 0; nt < 4; nt++)
                    mma_f16(acc[mt][nt][0], acc[mt][nt][1], acc[mt][nt][2], acc[mt][nt][3],
                            a[mt][0], a[mt][1], a[mt][2], a[mt][3],
                            b[nt >> 1][(nt & 1) * 2], b[nt >> 1][(nt & 1) * 2 + 1]);
        }

        CP_WAIT(GSTAGES - 2);
        buf  = (buf  == GSTAGES - 1) ? 0 : buf + 1;
        lbuf = (lbuf == GSTAGES - 1) ? 0 : lbuf + 1;
    }

    // ---- epilogue: lrelu + fp16 store ----
#pragma unroll
    for (int mt = 0; mt < 2; mt++) {
        int mrow = bm + wm * 32 + mt * 16 + g;
#pragma unroll
        for (int nt = 0; nt < 4; nt++) {
            int ncol = bn + wn * 32 + nt * 8 + t * 2;
            __half2 lo = __floats2half2_rn(lrelu(acc[mt][nt][0]), lrelu(acc[mt][nt][1]));
            __half2 hi = __floats2half2_rn(lrelu(acc[mt][nt][2]), lrelu(acc[mt][nt][3]));
            *reinterpret_cast<__half2*>(C + (size_t)mrow * FOUT + ncol)       = lo;
            *reinterpret_cast<__half2*>(C + (size_t)(mrow + 8) * FOUT + ncol) = hi;
        }
    }
}

// ---------------- kernel 3: GAT softmax epilogue (fp16 inputs) ----------------
__global__ void gat_epilogue_kernel(const __half* __restrict__ srcz,
                                    const __half* __restrict__ hz,
                                    const float*  __restrict__ a_attn,
                                    float*        __restrict__ msg)
{
    int n   = blockIdx.x;
    int tid = threadIdx.x;  // 288 = 9 warps
    int warp = tid >> 5, lane = tid & 31;

    __shared__ __half zs[RR][FOUT];   // 8 KB
    __shared__ __half hzs[FOUT];      // 1 KB
    __shared__ float scoresm[9];
    __shared__ float alpha[RR];

    const uint4* zp = reinterpret_cast<const uint4*>(srcz + (size_t)n * RR * FOUT);
    uint4* zsm = reinterpret_cast<uint4*>(&zs[0][0]);
    for (int i = tid; i < RR * FOUT / 8; i += 288) zsm[i] = zp[i];
    const uint4* hp = reinterpret_cast<const uint4*>(hz + (size_t)n * FOUT);
    uint4* hsm = reinterpret_cast<uint4*>(hzs);
    for (int i = tid; i < FOUT / 8; i += 288) hsm[i] = hp[i];
    __syncthreads();

    {
        const __half* src = (warp < 8) ? &zs[warp][0] : hzs;
        const float* av = a_attn + (warp < 8 ? 0 : FOUT);
        float s = 0.0f;
#pragma unroll
        for (int c = 0; c < 2; c++) {
            int base = (lane + c * 32) * 8;
            uint4 hv = *reinterpret_cast<const uint4*>(src + base);
            const __half2* hp2 = reinterpret_cast<const __half2*>(&hv);
            const float4* a4 = reinterpret_cast<const float4*>(av + base);
            float4 a0 = a4[0], a1 = a4[1];
            float2 z0 = __half22float2(hp2[0]);
            float2 z1 = __half22float2(hp2[1]);
            float2 z2 = __half22float2(hp2[2]);
            float2 z3 = __half22float2(hp2[3]);
            s += z0.x * a0.x + z0.y * a0.y + z1.x * a0.z + z1.y * a0.w;
            s += z2.x * a1.x + z2.y * a1.y + z3.x * a1.z + z3.y * a1.w;
        }
#pragma unroll
        for (int off = 16; off; off >>= 1)
            s += __shfl_down_sync(0xffffffffu, s, off);
        if (lane == 0) scoresm[warp] = s;
    }
    __syncthreads();

    if (tid == 0) {
        float sh = scoresm[8];
        float sc[RR], mx = -3.402823466e38f;
#pragma unroll
        for (int r = 0; r < RR; r++) {
            sc[r] = lrelu(scoresm[r] + sh);
            mx = fmaxf(mx, sc[r]);
        }
        float sum = 0.0f;
#pragma unroll
        for (int r = 0; r < RR; r++) {
            float e = expf(sc[r] - mx);
            alpha[r] = e;
            sum += e;
        }
        float inv = 1.0f / sum;
#pragma unroll
        for (int r = 0; r < RR; r++) alpha[r] *= inv;
    }
    __syncthreads();

    float al[RR];
#pragma unroll
    for (int r = 0; r < RR; r++) al[r] = alpha[r];

    for (int f = tid; f < FOUT; f += 288) {
        float acc = RESIDUAL * __half2float(hzs[f]);
#pragma unroll
        for (int r = 0; r < RR; r++) acc += al[r] * __half2float(zs[r][f]);
        msg[(size_t)n * FOUT + f] = acc;
    }
}

// ---------------- kernel 4: multi-attention + BatchNorm ----------------
__global__ void final_kernel(const float* __restrict__ Wp1,
                             const float* __restrict__ bp1,
                             const float* __restrict__ Wp2,
                             const float* __restrict__ bp2,
                             const float* __restrict__ gamma,
                             const float* __restrict__ betaBN,
                             const float* __restrict__ mean,
                             const float* __restrict__ var,
                             float*       __restrict__ out)
{
    int n   = blockIdx.x;
    int tid = threadIdx.x;  // 128

    __shared__ float z[2][FOUT];
    __shared__ float wred[4];
    __shared__ float betasm[2];

    for (int f = tid; f < FOUT; f += 128) {
        z[0][f] = g_msg[(size_t)n * FOUT + f];
        z[1][f] = g_msg[(size_t)NN * FOUT + (size_t)n * FOUT + f];
    }
    __syncthreads();

    int i  = tid >> 6;
    int hd = tid & 63;
    float acc = 0.0f;
#pragma unroll 8
    for (int k = 0; k < FOUT; k++) acc += z[i][k] * Wp1[k * HIDD + hd];
    float t  = tanhf(acc + bp1[hd]);
    float pw = t * Wp2[hd];

#pragma unroll
    for (int off = 16; off; off >>= 1)
        pw += __shfl_down_sync(0xffffffffu, pw, off);
    if ((tid & 31) == 0) wred[tid >> 5] = pw;
    __syncthreads();
    if (tid == 0) {
        float w0 = tanhf(wred[0] + wred[1] + bp2[0]);
        float w1 = tanhf(wred[2] + wred[3] + bp2[0]);
        float m  = fmaxf(w0, w1);
        float e0 = expf(w0 - m), e1 = expf(w1 - m);
        float inv = 1.0f / (e0 + e1);
        betasm[0] = e0 * inv;
        betasm[1] = e1 * inv;
    }
    __syncthreads();

    float b0 = betasm[0], b1 = betasm[1];
    for (int f = tid; f < FOUT; f += 128) {
        float v = b0 * z[0][f] + b1 * z[1][f];
        out[(size_t)n * FOUT + f] =
            (v - mean[f]) * rsqrtf(var[f] + BN_EPS) * gamma[f] + betaBN[f];
    }
}

// ---------------- launch ----------------
extern "C" void kernel_launch(void* const* d_in, const int* in_sizes, int n_in,
                              void* d_out, int out_size)
{
    const float* src_h     = (const float*)d_in[0];
    const float* src_h_img = (const float*)d_in[1];
    const int*   rel       = (const int*)  d_in[2];
    const float* h         = (const float*)d_in[3];
    const float* h_img     = (const float*)d_in[4];
    const float* W0        = (const float*)d_in[5];
    const float* a0        = (const float*)d_in[6];
    const float* W1        = (const float*)d_in[7];
    const float* a1        = (const float*)d_in[8];
    const float* Wp1       = (const float*)d_in[9];
    const float* bp1       = (const float*)d_in[10];
    const float* Wp2       = (const float*)d_in[11];
    const float* bp2       = (const float*)d_in[12];
    const float* gamma     = (const float*)d_in[13];
    const float* betaBN    = (const float*)d_in[14];
    const float* mean      = (const float*)d_in[15];
    const float* var       = (const float*)d_in[16];
    float* out = (float*)d_out;

    __half *att, *wt, *hconv, *srcz, *hz;
    float *msg;
    cudaGetSymbolAddress((void**)&att,   g_att);
    cudaGetSymbolAddress((void**)&srcz,  g_srcz);
    cudaGetSymbolAddress((void**)&hz,    g_hz);
    cudaGetSymbolAddress((void**)&msg,   g_msg);
    cudaGetSymbolAddress((void**)&wt,    g_wt);
    cudaGetSymbolAddress((void**)&hconv, g_hconv);

    static cudaStream_t s1 = nullptr;
    static cudaEvent_t eFork = nullptr, eJoin = nullptr;
    if (!s1) {
        cudaStreamCreateWithFlags(&s1, cudaStreamNonBlocking);
        cudaEventCreateWithFlags(&eFork, cudaEventDisableTiming);
        cudaEventCreateWithFlags(&eJoin, cudaEventDisableTiming);
        cudaFuncSetAttribute(gemm_tc_kernel,
                             cudaFuncAttributeMaxDynamicSharedMemorySize, GEMM_SMEM);
    }

    const float* srcs[2] = {src_h, src_h_img};
    const float* hs[2]   = {h, h_img};
    const float* Ws[2]   = {W0, W1};
    const float* as[2]   = {a0, a1};

    cudaEventRecord(eFork, 0);
    cudaStreamWaitEvent(s1, eFork, 0);

    for (int pass = 0; pass < 2; pass++) {
        cudaStream_t st = pass ? s1 : (cudaStream_t)0;
        __half* attP   = att   + (size_t)pass * NN * RR * FIN;
        __half* wtP    = wt    + (size_t)pass * FIN * FOUT;
        __half* hconvP = hconv + (size_t)pass * NN * FIN;
        __half* srczP  = srcz  + (size_t)pass * NN * RR * FOUT;
        __half* hzP    = hz    + (size_t)pass * NN * FOUT;

        transposeW_kernel<<<dim3(16, 16), dim3(32, 32), 0, st>>>(Ws[pass], wtP);
        convert_kernel<<<(NN * FIN / 4 + 255) / 256, 256, 0, st>>>(hs[pass], hconvP, NN * FIN / 4);
        maxpool_kernel<<<NN, 128, 0, st>>>(srcs[pass], rel, attP);
        gemm_tc_kernel<<<dim3(FOUT / 128, MBBIG + NN / 128), 512, GEMM_SMEM, st>>>(
            attP, hconvP, wtP, srczP, hzP);
        gat_epilogue_kernel<<<NN, 288, 0, st>>>(srczP, hzP, as[pass],
                                                msg + (size_t)pass * NN * FOUT);
    }

    cudaEventRecord(eJoin, s1);
    cudaStreamWaitEvent((cudaStream_t)0, eJoin, 0);
    final_kernel<<<NN, 128>>>(Wp1, bp1, Wp2, bp2, gamma, betaBN, mean, var, out);
}